// round 1
// baseline (speedup 1.0000x reference)
#include <cuda_runtime.h>
#include <math.h>

#define T_TOK 2048
#define H_DIM 2048
#define S_LEN 1024
#define NHEAD 16
#define E_NUM 16
#define I_DIM 1408
#define TWO_I 2816
#define SHI_DIM 2816
#define SH2 5632
#define QHD 192

// ---------------- scratch (device globals; no allocations allowed) ----------------
__device__ float g_X   [(size_t)T_TOK * H_DIM];      // rmsnorm1 output
__device__ float g_Q   [(size_t)T_TOK * 2048];       // q (nope part only), [t, head*128+d]
__device__ float g_KV  [(size_t)T_TOK * 4096];       // k (cols 0..2047), v (2048..4095)
__device__ float g_attn[(size_t)T_TOK * 2048];
__device__ float g_hid [(size_t)T_TOK * H_DIM];
__device__ float g_X2  [(size_t)T_TOK * H_DIM];
__device__ float g_sgu [(size_t)T_TOK * SH2];        // shared gu; act overwrites first SHI cols
__device__ float g_gu  [(size_t)E_NUM * T_TOK * TWO_I];  // per-expert gu; act overwrites first I cols
__device__ float g_down[(size_t)E_NUM * T_TOK * H_DIM];  // per-(expert,row) down output
__device__ int   g_cnt [E_NUM];
__device__ int   g_tok [E_NUM * T_TOK];
__device__ int   g_texp[T_TOK * 4];
__device__ int   g_trow[T_TOK * 4];
__device__ float g_twt [T_TOK * 4];

// ---------------- rmsnorm ----------------
__global__ __launch_bounds__(256) void rmsnorm_kernel(const float* __restrict__ in,
                                                      const float* __restrict__ w,
                                                      float* __restrict__ out) {
    int t = blockIdx.x;
    const float* row = in + (size_t)t * H_DIM;
    float ss = 0.f;
    for (int i = threadIdx.x; i < H_DIM; i += 256) { float v = row[i]; ss += v * v; }
    __shared__ float red[8];
    #pragma unroll
    for (int o = 16; o; o >>= 1) ss += __shfl_xor_sync(0xffffffffu, ss, o);
    if ((threadIdx.x & 31) == 0) red[threadIdx.x >> 5] = ss;
    __syncthreads();
    if (threadIdx.x < 32) {
        float v = (threadIdx.x < 8) ? red[threadIdx.x] : 0.f;
        #pragma unroll
        for (int o = 4; o; o >>= 1) v += __shfl_xor_sync(0xffffffffu, v, o);
        if (threadIdx.x == 0) red[0] = v;
    }
    __syncthreads();
    float inv = rsqrtf(red[0] * (1.0f / H_DIM) + 1e-6f);
    for (int i = threadIdx.x; i < H_DIM; i += 256)
        out[(size_t)t * H_DIM + i] = row[i] * inv * w[i];
}

// ---------------- generic SGEMM: C[M,N] = A[M,K] * W[N,K]^T (+ addsrc) ----------------
// 128x128 tile, BK=8, 256 threads, 8x8 per-thread microtile.
template <bool QMAP>
__global__ void __launch_bounds__(256) gemm128(const float* __restrict__ A, int lda,
                                               const float* __restrict__ W, int ldw,
                                               float* __restrict__ C, int ldc,
                                               int M, int N, int K,
                                               const float* __restrict__ addsrc, int ldadd) {
    __shared__ float As[8][128];
    __shared__ float Bs[8][128];
    int bm = blockIdx.y * 128, bn = blockIdx.x * 128;
    int tid = threadIdx.x;
    int tr = tid / 16, tc = tid % 16;
    int arow = tid >> 1, acol = (tid & 1) * 4;
    float acc[8][8];
    #pragma unroll
    for (int i = 0; i < 8; i++)
        #pragma unroll
        for (int j = 0; j < 8; j++) acc[i][j] = 0.f;

    const float* arowp = (bm + arow < M) ? (A + (size_t)(bm + arow) * lda) : nullptr;
    int n = bn + arow;
    int wr = QMAP ? ((n >> 7) * QHD + (n & 127)) : n;
    const float* wrowp = (n < N) ? (W + (size_t)wr * ldw) : nullptr;

    for (int k0 = 0; k0 < K; k0 += 8) {
        float4 va = make_float4(0.f, 0.f, 0.f, 0.f);
        if (arowp) va = *(const float4*)(arowp + k0 + acol);
        As[acol + 0][arow] = va.x; As[acol + 1][arow] = va.y;
        As[acol + 2][arow] = va.z; As[acol + 3][arow] = va.w;
        float4 vb = make_float4(0.f, 0.f, 0.f, 0.f);
        if (wrowp) vb = *(const float4*)(wrowp + k0 + acol);
        Bs[acol + 0][arow] = vb.x; Bs[acol + 1][arow] = vb.y;
        Bs[acol + 2][arow] = vb.z; Bs[acol + 3][arow] = vb.w;
        __syncthreads();
        #pragma unroll
        for (int k = 0; k < 8; k++) {
            float ra[8], rb[8];
            #pragma unroll
            for (int i = 0; i < 8; i++) ra[i] = As[k][tr * 8 + i];
            #pragma unroll
            for (int j = 0; j < 8; j++) rb[j] = Bs[k][tc * 8 + j];
            #pragma unroll
            for (int i = 0; i < 8; i++)
                #pragma unroll
                for (int j = 0; j < 8; j++) acc[i][j] += ra[i] * rb[j];
        }
        __syncthreads();
    }
    #pragma unroll
    for (int i = 0; i < 8; i++) {
        int m = bm + tr * 8 + i;
        if (m >= M) continue;
        #pragma unroll
        for (int j = 0; j < 8; j++) {
            int nn = bn + tc * 8 + j;
            if (nn >= N) continue;
            float v = acc[i][j];
            if (addsrc) v += addsrc[(size_t)m * ldadd + nn];
            C[(size_t)m * ldc + nn] = v;
        }
    }
}

// ---------------- grouped MoE GEMM (per-expert, device-side M) ----------------
template <bool GATHER>
__global__ void __launch_bounds__(256) gemm_moe(const float* __restrict__ Abase, long long astride, int lda,
                                                const float* __restrict__ Wbase, long long wstride, int ldw,
                                                float* __restrict__ Cbase, long long cstride, int ldc,
                                                int N, int K) {
    int e = blockIdx.z;
    int M = g_cnt[e];
    int bm = blockIdx.y * 128, bn = blockIdx.x * 128;
    if (bm >= M) return;
    const float* W = Wbase + (long long)e * wstride;
    float* C = Cbase + (long long)e * cstride;

    __shared__ float As[8][128];
    __shared__ float Bs[8][128];
    int tid = threadIdx.x;
    int tr = tid / 16, tc = tid % 16;
    int arow = tid >> 1, acol = (tid & 1) * 4;
    float acc[8][8];
    #pragma unroll
    for (int i = 0; i < 8; i++)
        #pragma unroll
        for (int j = 0; j < 8; j++) acc[i][j] = 0.f;

    const float* arowp = nullptr;
    int m0 = bm + arow;
    if (m0 < M) {
        if (GATHER) arowp = Abase + (size_t)g_tok[e * T_TOK + m0] * lda;
        else        arowp = Abase + (long long)e * astride + (size_t)m0 * lda;
    }
    const float* wrowp = W + (size_t)(bn + arow) * ldw;

    for (int k0 = 0; k0 < K; k0 += 8) {
        float4 va = make_float4(0.f, 0.f, 0.f, 0.f);
        if (arowp) va = *(const float4*)(arowp + k0 + acol);
        As[acol + 0][arow] = va.x; As[acol + 1][arow] = va.y;
        As[acol + 2][arow] = va.z; As[acol + 3][arow] = va.w;
        float4 vb = *(const float4*)(wrowp + k0 + acol);
        Bs[acol + 0][arow] = vb.x; Bs[acol + 1][arow] = vb.y;
        Bs[acol + 2][arow] = vb.z; Bs[acol + 3][arow] = vb.w;
        __syncthreads();
        #pragma unroll
        for (int k = 0; k < 8; k++) {
            float ra[8], rb[8];
            #pragma unroll
            for (int i = 0; i < 8; i++) ra[i] = As[k][tr * 8 + i];
            #pragma unroll
            for (int j = 0; j < 8; j++) rb[j] = Bs[k][tc * 8 + j];
            #pragma unroll
            for (int i = 0; i < 8; i++)
                #pragma unroll
                for (int j = 0; j < 8; j++) acc[i][j] += ra[i] * rb[j];
        }
        __syncthreads();
    }
    #pragma unroll
    for (int i = 0; i < 8; i++) {
        int m = bm + tr * 8 + i;
        if (m >= M) continue;
        #pragma unroll
        for (int j = 0; j < 8; j++)
            C[(size_t)m * ldc + bn + tc * 8 + j] = acc[i][j];
    }
}

// ---------------- flash attention (fp32, causal, D=128, 64x64 tiles) ----------------
__global__ void __launch_bounds__(256) attn_kernel() {
    extern __shared__ float sm[];
    float* Qs = sm;                 // [64][129]
    float* Ks = Qs + 64 * 129;      // [64][129]
    float* Vs = Ks + 64 * 129;      // [64][132]
    float* Ps = Vs + 64 * 132;      // [64][65]
    float* mrow = Ps + 64 * 65;
    float* lrow = mrow + 64;
    float* corr = lrow + 64;

    int bh = blockIdx.y; int b = bh >> 4, h = bh & 15;
    int q0 = blockIdx.x * 64;
    int tb = b * S_LEN;
    int tid = threadIdx.x;
    int ty = tid / 16, tx = tid % 16;

    for (int i = tid; i < 64 * 32; i += 256) {
        int r = i >> 5, c4 = (i & 31) * 4;
        float4 v = *(const float4*)(g_Q + (size_t)(tb + q0 + r) * 2048 + h * 128 + c4);
        Qs[r * 129 + c4] = v.x; Qs[r * 129 + c4 + 1] = v.y;
        Qs[r * 129 + c4 + 2] = v.z; Qs[r * 129 + c4 + 3] = v.w;
    }
    if (tid < 64) { mrow[tid] = -1e30f; lrow[tid] = 0.f; }
    float acc[4][8];
    #pragma unroll
    for (int i = 0; i < 4; i++)
        #pragma unroll
        for (int j = 0; j < 8; j++) acc[i][j] = 0.f;
    const float scale = 1.0f / sqrtf(192.0f);
    __syncthreads();

    int nkt = blockIdx.x + 1;
    for (int kt = 0; kt < nkt; kt++) {
        int k0 = kt * 64;
        for (int i = tid; i < 64 * 32; i += 256) {
            int r = i >> 5, c4 = (i & 31) * 4;
            const float* kp = g_KV + (size_t)(tb + k0 + r) * 4096 + h * 128;
            float4 kv4 = *(const float4*)(kp + c4);
            Ks[r * 129 + c4] = kv4.x; Ks[r * 129 + c4 + 1] = kv4.y;
            Ks[r * 129 + c4 + 2] = kv4.z; Ks[r * 129 + c4 + 3] = kv4.w;
            float4 vv4 = *(const float4*)(kp + 2048 + c4);
            Vs[r * 132 + c4] = vv4.x; Vs[r * 132 + c4 + 1] = vv4.y;
            Vs[r * 132 + c4 + 2] = vv4.z; Vs[r * 132 + c4 + 3] = vv4.w;
        }
        __syncthreads();
        float s[4][4];
        #pragma unroll
        for (int i = 0; i < 4; i++)
            #pragma unroll
            for (int j = 0; j < 4; j++) s[i][j] = 0.f;
        #pragma unroll 4
        for (int k = 0; k < 128; k++) {
            float qa[4], kb[4];
            #pragma unroll
            for (int i = 0; i < 4; i++) qa[i] = Qs[(4 * ty + i) * 129 + k];
            #pragma unroll
            for (int j = 0; j < 4; j++) kb[j] = Ks[(4 * tx + j) * 129 + k];
            #pragma unroll
            for (int i = 0; i < 4; i++)
                #pragma unroll
                for (int j = 0; j < 4; j++) s[i][j] += qa[i] * kb[j];
        }
        #pragma unroll
        for (int i = 0; i < 4; i++)
            #pragma unroll
            for (int j = 0; j < 4; j++) {
                int rq = q0 + 4 * ty + i, ck = k0 + 4 * tx + j;
                Ps[(4 * ty + i) * 65 + 4 * tx + j] = (ck <= rq) ? s[i][j] * scale : -1e30f;
            }
        __syncthreads();
        if (tid < 64) {
            float m0 = mrow[tid], mx = m0;
            for (int c = 0; c < 64; c++) mx = fmaxf(mx, Ps[tid * 65 + c]);
            float cr = __expf(m0 - mx);
            float l = lrow[tid] * cr;
            for (int c = 0; c < 64; c++) {
                float p = __expf(Ps[tid * 65 + c] - mx);
                Ps[tid * 65 + c] = p; l += p;
            }
            mrow[tid] = mx; lrow[tid] = l; corr[tid] = cr;
        }
        __syncthreads();
        #pragma unroll
        for (int i = 0; i < 4; i++) {
            float cr = corr[4 * ty + i];
            #pragma unroll
            for (int j = 0; j < 8; j++) acc[i][j] *= cr;
        }
        #pragma unroll 2
        for (int c = 0; c < 64; c++) {
            float p[4], v[8];
            #pragma unroll
            for (int i = 0; i < 4; i++) p[i] = Ps[(4 * ty + i) * 65 + c];
            #pragma unroll
            for (int j = 0; j < 8; j++) v[j] = Vs[c * 132 + 8 * tx + j];
            #pragma unroll
            for (int i = 0; i < 4; i++)
                #pragma unroll
                for (int j = 0; j < 8; j++) acc[i][j] += p[i] * v[j];
        }
        __syncthreads();
    }
    #pragma unroll
    for (int i = 0; i < 4; i++) {
        int r = 4 * ty + i;
        float inv = 1.0f / lrow[r];
        #pragma unroll
        for (int j = 0; j < 8; j++)
            g_attn[(size_t)(tb + q0 + r) * 2048 + h * 128 + 8 * tx + j] = acc[i][j] * inv;
    }
}

// ---------------- gate: logits, softmax, top4, renorm, build expert lists ----------------
__global__ void __launch_bounds__(512) zero_cnt() { if (threadIdx.x < E_NUM) g_cnt[threadIdx.x] = 0; }

__global__ void __launch_bounds__(512) gate_kernel(const float* __restrict__ gate_w) {
    int t = blockIdx.x;
    int w = threadIdx.x >> 5, lane = threadIdx.x & 31;
    const float* x = g_X2 + (size_t)t * H_DIM;
    const float* gw = gate_w + (size_t)w * H_DIM;
    float s = 0.f;
    for (int i = lane; i < H_DIM; i += 32) s += x[i] * gw[i];
    #pragma unroll
    for (int o = 16; o; o >>= 1) s += __shfl_xor_sync(0xffffffffu, s, o);
    __shared__ float lg[E_NUM];
    if (lane == 0) lg[w] = s;
    __syncthreads();
    if (threadIdx.x == 0) {
        float mx = -1e30f;
        for (int e = 0; e < E_NUM; e++) mx = fmaxf(mx, lg[e]);
        float pe[E_NUM];
        for (int e = 0; e < E_NUM; e++) pe[e] = expf(lg[e] - mx);
        bool used[E_NUM];
        for (int e = 0; e < E_NUM; e++) used[e] = false;
        int sel[4]; float sw[4]; float wsum = 0.f;
        for (int j = 0; j < 4; j++) {
            int bi = -1; float bv = -1.f;
            for (int e = 0; e < E_NUM; e++)
                if (!used[e] && pe[e] > bv) { bv = pe[e]; bi = e; }
            used[bi] = true; sel[j] = bi; sw[j] = bv; wsum += bv;
        }
        for (int j = 0; j < 4; j++) {
            int e = sel[j];
            int pos = atomicAdd(&g_cnt[e], 1);
            g_tok[e * T_TOK + pos] = t;
            g_texp[t * 4 + j] = e;
            g_trow[t * 4 + j] = pos;
            g_twt [t * 4 + j] = sw[j] / wsum;
        }
    }
}

// ---------------- activation kernels ----------------
__device__ __forceinline__ float silu_f(float x) { return x / (1.0f + __expf(-x)); }

__global__ void __launch_bounds__(256) act_moe() {
    int e = blockIdx.y;
    int r = blockIdx.x;
    if (r >= g_cnt[e]) return;
    float* row = g_gu + ((size_t)e * T_TOK + r) * TWO_I;
    for (int i = threadIdx.x; i < I_DIM; i += 256) {
        float g = row[i], u = row[I_DIM + i];
        row[i] = silu_f(g) * u;
    }
}

__global__ void __launch_bounds__(256) act_shared() {
    int t = blockIdx.x;
    float* row = g_sgu + (size_t)t * SH2;
    for (int i = threadIdx.x; i < SHI_DIM; i += 256) {
        float g = row[i], u = row[SHI_DIM + i];
        row[i] = silu_f(g) * u;
    }
}

// ---------------- final: out(=hid+shared) += sum_j w_j * down[e_j][r_j] ----------------
__global__ void __launch_bounds__(256) final_sum(float* __restrict__ out) {
    int t = blockIdx.x;
    int e0 = g_texp[t * 4 + 0], e1 = g_texp[t * 4 + 1], e2 = g_texp[t * 4 + 2], e3 = g_texp[t * 4 + 3];
    int r0 = g_trow[t * 4 + 0], r1 = g_trow[t * 4 + 1], r2 = g_trow[t * 4 + 2], r3 = g_trow[t * 4 + 3];
    float w0 = g_twt[t * 4 + 0], w1v = g_twt[t * 4 + 1], w2v = g_twt[t * 4 + 2], w3 = g_twt[t * 4 + 3];
    const float* d0 = g_down + ((size_t)e0 * T_TOK + r0) * H_DIM;
    const float* d1 = g_down + ((size_t)e1 * T_TOK + r1) * H_DIM;
    const float* d2 = g_down + ((size_t)e2 * T_TOK + r2) * H_DIM;
    const float* d3 = g_down + ((size_t)e3 * T_TOK + r3) * H_DIM;
    for (int h = threadIdx.x; h < H_DIM; h += 256) {
        float v = out[(size_t)t * H_DIM + h];
        v += w0 * d0[h] + w1v * d1[h] + w2v * d2[h] + w3 * d3[h];
        out[(size_t)t * H_DIM + h] = v;
    }
}

// ---------------- launch ----------------
extern "C" void kernel_launch(void* const* d_in, const int* in_sizes, int n_in,
                              void* d_out, int out_size) {
    (void)in_sizes; (void)n_in; (void)out_size;
    const float* hidden  = (const float*)d_in[0];
    const float* ln1_w   = (const float*)d_in[2];
    const float* ln2_w   = (const float*)d_in[3];
    const float* q_w     = (const float*)d_in[4];
    const float* kv_w    = (const float*)d_in[5];
    const float* o_w     = (const float*)d_in[6];
    const float* gate_w  = (const float*)d_in[7];
    const float* w1      = (const float*)d_in[8];
    const float* w2      = (const float*)d_in[9];
    const float* sh_gu_w = (const float*)d_in[10];
    const float* sh_dn_w = (const float*)d_in[11];
    float* out = (float*)d_out;

    float *pX, *pQ, *pKV, *pAttn, *pHid, *pX2, *pSgu, *pGu, *pDown;
    cudaGetSymbolAddress((void**)&pX, g_X);
    cudaGetSymbolAddress((void**)&pQ, g_Q);
    cudaGetSymbolAddress((void**)&pKV, g_KV);
    cudaGetSymbolAddress((void**)&pAttn, g_attn);
    cudaGetSymbolAddress((void**)&pHid, g_hid);
    cudaGetSymbolAddress((void**)&pX2, g_X2);
    cudaGetSymbolAddress((void**)&pSgu, g_sgu);
    cudaGetSymbolAddress((void**)&pGu, g_gu);
    cudaGetSymbolAddress((void**)&pDown, g_down);

    const int ATTN_SMEM = (64 * 129 + 64 * 129 + 64 * 132 + 64 * 65 + 192) * 4;
    cudaFuncSetAttribute(attn_kernel, cudaFuncAttributeMaxDynamicSharedMemorySize, ATTN_SMEM);

    // 1) x = rmsnorm(hidden, ln1_w)
    rmsnorm_kernel<<<T_TOK, 256>>>(hidden, ln1_w, pX);
    // 2) Q (nope rows only, gathered from q_w)
    gemm128<true><<<dim3(16, 16), 256>>>(pX, H_DIM, q_w, H_DIM, pQ, 2048,
                                         T_TOK, 2048, H_DIM, nullptr, 0);
    // 3) KV (first 4096 rows of kv_w; rope tail unused)
    gemm128<false><<<dim3(32, 16), 256>>>(pX, H_DIM, kv_w, H_DIM, pKV, 4096,
                                          T_TOK, 4096, H_DIM, nullptr, 0);
    // 4) causal flash attention
    attn_kernel<<<dim3(16, 32), 256, ATTN_SMEM>>>();
    // 5) hid = attn @ o_w^T + hidden
    gemm128<false><<<dim3(16, 16), 256>>>(pAttn, 2048, o_w, 2048, pHid, H_DIM,
                                          T_TOK, H_DIM, 2048, hidden, H_DIM);
    // 6) x2 = rmsnorm(hid, ln2_w)
    rmsnorm_kernel<<<T_TOK, 256>>>(pHid, ln2_w, pX2);
    // 7) routing
    zero_cnt<<<1, 32>>>();
    gate_kernel<<<T_TOK, 512>>>(gate_w);
    // 8) routed GU (top-4 only, grouped per expert)
    gemm_moe<true><<<dim3(TWO_I / 128, 16, E_NUM), 256>>>(
        pX2, 0LL, H_DIM,
        w1, (long long)TWO_I * H_DIM, H_DIM,
        pGu, (long long)T_TOK * TWO_I, TWO_I,
        TWO_I, H_DIM);
    // 9) routed act
    act_moe<<<dim3(T_TOK, E_NUM), 256>>>();
    // 10) routed down -> per-slot buffer
    gemm_moe<false><<<dim3(H_DIM / 128, 16, E_NUM), 256>>>(
        pGu, (long long)T_TOK * TWO_I, TWO_I,
        w2, (long long)H_DIM * I_DIM, I_DIM,
        pDown, (long long)T_TOK * H_DIM, H_DIM,
        H_DIM, I_DIM);
    // 11) shared GU
    gemm128<false><<<dim3(SH2 / 128, 16), 256>>>(pX2, H_DIM, sh_gu_w, H_DIM, pSgu, SH2,
                                                 T_TOK, SH2, H_DIM, nullptr, 0);
    // 12) shared act
    act_shared<<<T_TOK, 256>>>();
    // 13) out = hid + shared_down
    gemm128<false><<<dim3(16, 16), 256>>>(pSgu, SH2, sh_dn_w, SHI_DIM, out, H_DIM,
                                          T_TOK, H_DIM, SHI_DIM, pHid, H_DIM);
    // 14) out += weighted routed contributions (fixed order -> deterministic)
    final_sum<<<T_TOK, 256>>>(out);
}

// round 3
// speedup vs baseline: 2.1011x; 2.1011x over previous
#include <cuda_runtime.h>
#include <cuda_bf16.h>
#include <cstdint>
#include <math.h>

#define T_TOK 2048
#define H_DIM 2048
#define S_LEN 1024
#define NHEAD 16
#define E_NUM 16
#define I_DIM 1408
#define TWO_I 2816
#define SHI_DIM 2816
#define SH2 5632

// ---------------- scratch (device globals; no allocations allowed) ----------------
__device__ float g_X   [(size_t)T_TOK * H_DIM];
__device__ float g_Q   [(size_t)T_TOK * 2048];
__device__ float g_KV  [(size_t)T_TOK * 4096];
__device__ float g_attn[(size_t)T_TOK * 2048];
__device__ float g_hid [(size_t)T_TOK * H_DIM];
__device__ float g_X2  [(size_t)T_TOK * H_DIM];
__device__ float g_sgu [(size_t)T_TOK * SH2];
__device__ float g_gu  [(size_t)E_NUM * T_TOK * TWO_I];
__device__ float g_down[(size_t)E_NUM * T_TOK * H_DIM];
__device__ int   g_cnt [E_NUM];
__device__ int   g_tok [E_NUM * T_TOK];
__device__ int   g_texp[T_TOK * 4];
__device__ int   g_trow[T_TOK * 4];
__device__ float g_twt [T_TOK * 4];

// ================= helpers =================
static __device__ __forceinline__ uint32_t smem_u32(const void* p) {
    uint32_t a;
    asm("{ .reg .u64 t; cvta.to.shared.u64 t, %1; cvt.u32.u64 %0, t; }" : "=r"(a) : "l"(p));
    return a;
}
// bf16 hi/lo split: x = hi(trunc) + lo(rn); packs 2 consecutive elements into b32
static __device__ __forceinline__ uint32_t hi2(float x, float y) {
    uint32_t r;
    asm("prmt.b32 %0, %1, %2, 0x7632;" : "=r"(r) : "r"(__float_as_uint(x)), "r"(__float_as_uint(y)));
    return r;  // (hi(y)<<16) | hi(x)
}
static __device__ __forceinline__ uint32_t lo2(float x, float y, uint32_t h) {
    float hx = __uint_as_float(h << 16);
    float hy = __uint_as_float(h & 0xffff0000u);
    float lx = x - hx, ly = y - hy;
    uint32_t r;
    asm("cvt.rn.bf16x2.f32 %0, %1, %2;" : "=r"(r) : "f"(ly), "f"(lx));
    return r;
}
#define LDM4(r, a) \
    asm volatile("ldmatrix.sync.aligned.m8n8.x4.shared.b16 {%0,%1,%2,%3}, [%4];" \
        : "=r"((r)[0]), "=r"((r)[1]), "=r"((r)[2]), "=r"((r)[3]) : "r"(a))
#define MMA16816(c, a, b0, b1) \
    asm volatile("mma.sync.aligned.m16n8k16.row.col.f32.bf16.bf16.f32 " \
        "{%0,%1,%2,%3}, {%4,%5,%6,%7}, {%8,%9}, {%0,%1,%2,%3};" \
        : "+f"((c)[0]), "+f"((c)[1]), "+f"((c)[2]), "+f"((c)[3]) \
        : "r"((a)[0]), "r"((a)[1]), "r"((a)[2]), "r"((a)[3]), "r"(b0), "r"(b1))

// ================= HMMA bf16x3 GEMM: C[M,N] = A[M,K] @ W[N,K]^T (+addsrc) =================
// 128x128 tile/CTA, BK=32 fp32, 8 warps (warp tile 32x64), double-buffered SMEM.
// SMEM stage: Ahi[128x32bf16 rows @80B] Alo Bhi Blo  (10240B each, 40960/stage, 2 stages)
// MODE: 0=plain(M arg), 1=MoE gather A rows via g_tok, 2=MoE grouped A base. QMAP remaps W rows for q_w.
#define GSMEM_BYTES (2 * 40960)

template <int MODE, bool QMAP, bool ADD>
__global__ void __launch_bounds__(256, 1) gemm_mma(
    const float* __restrict__ A, long long astride, int lda,
    const float* __restrict__ W, long long wstride, int ldw,
    float* __restrict__ C, long long cstride, int ldc,
    int M, int K,
    const float* __restrict__ addsrc, int ldadd)
{
    extern __shared__ char smem[];
    const int e  = blockIdx.z;
    const int Me = (MODE == 0) ? M : g_cnt[e];
    const int bm = blockIdx.y * 128, bn = blockIdx.x * 128;
    if (bm >= Me) return;
    const float* Ab = A + (MODE == 2 ? (long long)e * astride : 0LL);
    const float* Wb = W + (long long)e * wstride;
    float*       Cb = C + (long long)e * cstride;

    const uint32_t sb = smem_u32(smem);
    const int tid = threadIdx.x, wid = tid >> 5, lid = tid & 31;
    const int wm = wid & 3, wn = wid >> 2;   // warp grid 4(M) x 2(N)

    // ---- staging pointers: 2 groups/thread per matrix, each 8 consecutive k floats ----
    const float* aPtr[2]; const float* bPtr[2];
    uint32_t stsA[2], stsB[2];
    #pragma unroll
    for (int i = 0; i < 2; i++) {
        int q = tid + i * 256;           // 0..511
        int row = q >> 2, kq = (q & 3) * 8;
        stsA[i] = row * 80 + kq * 2;
        stsB[i] = 20480 + row * 80 + kq * 2;
        int gm = bm + row;
        long long arow;
        if (MODE == 1)      arow = (gm < Me) ? (long long)g_tok[e * T_TOK + gm] : (long long)g_tok[e * T_TOK];
        else                arow = (gm < Me) ? (long long)gm : 0LL;
        aPtr[i] = Ab + arow * (long long)lda + kq;
        int n = bn + row;
        int wr = QMAP ? ((n >> 7) * 192 + (n & 127)) : n;
        bPtr[i] = Wb + (long long)wr * (long long)ldw + kq;
    }

    // ---- ldmatrix fragment offsets ----
    const int laneRow = lid & 15, laneChk = lid >> 4;
    uint32_t aOff[2], bOff[4];
    #pragma unroll
    for (int t = 0; t < 2; t++)
        aOff[t] = (uint32_t)((wm * 32 + t * 16 + laneRow) * 80 + laneChk * 16);
    #pragma unroll
    for (int p = 0; p < 4; p++)
        bOff[p] = (uint32_t)(20480 + (wn * 64 + p * 16 + laneRow) * 80 + laneChk * 16);

    float acc[2][8][4];
    #pragma unroll
    for (int t = 0; t < 2; t++)
        #pragma unroll
        for (int n8 = 0; n8 < 8; n8++)
            #pragma unroll
            for (int j = 0; j < 4; j++) acc[t][n8][j] = 0.f;

    const int NC = K / 32;
    float4 ra[2][2], rb[2][2];
    #pragma unroll
    for (int i = 0; i < 2; i++) {
        ra[i][0] = *(const float4*)(aPtr[i]);     ra[i][1] = *(const float4*)(aPtr[i] + 4);
        rb[i][0] = *(const float4*)(bPtr[i]);     rb[i][1] = *(const float4*)(bPtr[i] + 4);
    }

    for (int c = 0; c < NC; c++) {
        const uint32_t stg = sb + (uint32_t)(c & 1) * 40960u;
        // store staged chunk (hi/lo split)
        #pragma unroll
        for (int i = 0; i < 2; i++) {
            uint32_t h0 = hi2(ra[i][0].x, ra[i][0].y), h1 = hi2(ra[i][0].z, ra[i][0].w);
            uint32_t h2 = hi2(ra[i][1].x, ra[i][1].y), h3 = hi2(ra[i][1].z, ra[i][1].w);
            uint32_t l0 = lo2(ra[i][0].x, ra[i][0].y, h0), l1 = lo2(ra[i][0].z, ra[i][0].w, h1);
            uint32_t l2 = lo2(ra[i][1].x, ra[i][1].y, h2), l3 = lo2(ra[i][1].z, ra[i][1].w, h3);
            asm volatile("st.shared.v4.b32 [%0], {%1,%2,%3,%4};" :: "r"(stg + stsA[i]),          "r"(h0), "r"(h1), "r"(h2), "r"(h3) : "memory");
            asm volatile("st.shared.v4.b32 [%0], {%1,%2,%3,%4};" :: "r"(stg + stsA[i] + 10240u), "r"(l0), "r"(l1), "r"(l2), "r"(l3) : "memory");
            uint32_t g0 = hi2(rb[i][0].x, rb[i][0].y), g1 = hi2(rb[i][0].z, rb[i][0].w);
            uint32_t g2 = hi2(rb[i][1].x, rb[i][1].y), g3 = hi2(rb[i][1].z, rb[i][1].w);
            uint32_t m0 = lo2(rb[i][0].x, rb[i][0].y, g0), m1 = lo2(rb[i][0].z, rb[i][0].w, g1);
            uint32_t m2 = lo2(rb[i][1].x, rb[i][1].y, g2), m3 = lo2(rb[i][1].z, rb[i][1].w, g3);
            asm volatile("st.shared.v4.b32 [%0], {%1,%2,%3,%4};" :: "r"(stg + stsB[i]),          "r"(g0), "r"(g1), "r"(g2), "r"(g3) : "memory");
            asm volatile("st.shared.v4.b32 [%0], {%1,%2,%3,%4};" :: "r"(stg + stsB[i] + 10240u), "r"(m0), "r"(m1), "r"(m2), "r"(m3) : "memory");
        }
        __syncthreads();
        // prefetch next chunk
        if (c + 1 < NC) {
            int k0 = (c + 1) * 32;
            #pragma unroll
            for (int i = 0; i < 2; i++) {
                ra[i][0] = *(const float4*)(aPtr[i] + k0);     ra[i][1] = *(const float4*)(aPtr[i] + k0 + 4);
                rb[i][0] = *(const float4*)(bPtr[i] + k0);     rb[i][1] = *(const float4*)(bPtr[i] + k0 + 4);
            }
        }
        // MMA: 2 k16 steps x 3 split terms
        #pragma unroll
        for (int h = 0; h < 2; h++) {
            uint32_t ah0[4], ah1[4], al0[4], al1[4];
            LDM4(ah0, stg + aOff[0] + h * 32);
            LDM4(ah1, stg + aOff[1] + h * 32);
            LDM4(al0, stg + aOff[0] + 10240u + h * 32);
            LDM4(al1, stg + aOff[1] + 10240u + h * 32);
            #pragma unroll
            for (int p = 0; p < 4; p++) {
                uint32_t bh[4], bl[4];
                LDM4(bh, stg + bOff[p] + h * 32);
                MMA16816(acc[0][2 * p],     ah0, bh[0], bh[2]);
                MMA16816(acc[0][2 * p + 1], ah0, bh[1], bh[3]);
                MMA16816(acc[1][2 * p],     ah1, bh[0], bh[2]);
                MMA16816(acc[1][2 * p + 1], ah1, bh[1], bh[3]);
                MMA16816(acc[0][2 * p],     al0, bh[0], bh[2]);
                MMA16816(acc[0][2 * p + 1], al0, bh[1], bh[3]);
                MMA16816(acc[1][2 * p],     al1, bh[0], bh[2]);
                MMA16816(acc[1][2 * p + 1], al1, bh[1], bh[3]);
                LDM4(bl, stg + bOff[p] + 10240u + h * 32);
                MMA16816(acc[0][2 * p],     ah0, bl[0], bl[2]);
                MMA16816(acc[0][2 * p + 1], ah0, bl[1], bl[3]);
                MMA16816(acc[1][2 * p],     ah1, bl[0], bl[2]);
                MMA16816(acc[1][2 * p + 1], ah1, bl[1], bl[3]);
            }
        }
        __syncthreads();
    }

    // ---- epilogue ----
    const int g = lid >> 2, tg = lid & 3;
    #pragma unroll
    for (int t = 0; t < 2; t++) {
        #pragma unroll
        for (int half = 0; half < 2; half++) {
            int row = bm + wm * 32 + t * 16 + g + half * 8;
            if (row >= Me) continue;
            float* cp = Cb + (long long)row * ldc + bn + wn * 64 + tg * 2;
            const float* ap = ADD ? (addsrc + (long long)row * ldadd + bn + wn * 64 + tg * 2) : (const float*)0;
            #pragma unroll
            for (int n8 = 0; n8 < 8; n8++) {
                float v0 = acc[t][n8][half * 2], v1 = acc[t][n8][half * 2 + 1];
                if (ADD) { v0 += ap[n8 * 8]; v1 += ap[n8 * 8 + 1]; }
                cp[n8 * 8] = v0; cp[n8 * 8 + 1] = v1;
            }
        }
    }
}

// ---------------- rmsnorm ----------------
__global__ __launch_bounds__(256) void rmsnorm_kernel(const float* __restrict__ in,
                                                      const float* __restrict__ w,
                                                      float* __restrict__ out) {
    int t = blockIdx.x;
    const float* row = in + (size_t)t * H_DIM;
    float ss = 0.f;
    for (int i = threadIdx.x; i < H_DIM; i += 256) { float v = row[i]; ss += v * v; }
    __shared__ float red[8];
    #pragma unroll
    for (int o = 16; o; o >>= 1) ss += __shfl_xor_sync(0xffffffffu, ss, o);
    if ((threadIdx.x & 31) == 0) red[threadIdx.x >> 5] = ss;
    __syncthreads();
    if (threadIdx.x < 32) {
        float v = (threadIdx.x < 8) ? red[threadIdx.x] : 0.f;
        #pragma unroll
        for (int o = 4; o; o >>= 1) v += __shfl_xor_sync(0xffffffffu, v, o);
        if (threadIdx.x == 0) red[0] = v;
    }
    __syncthreads();
    float inv = rsqrtf(red[0] * (1.0f / H_DIM) + 1e-6f);
    for (int i = threadIdx.x; i < H_DIM; i += 256)
        out[(size_t)t * H_DIM + i] = row[i] * inv * w[i];
}

// ---------------- flash attention (fp32, causal, D=128, 64x64 tiles) ----------------
__global__ void __launch_bounds__(256) attn_kernel() {
    extern __shared__ float sm[];
    float* Qs = sm;
    float* Ks = Qs + 64 * 129;
    float* Vs = Ks + 64 * 129;
    float* Ps = Vs + 64 * 132;
    float* mrow = Ps + 64 * 65;
    float* lrow = mrow + 64;
    float* corr = lrow + 64;

    int bh = blockIdx.y; int b = bh >> 4, h = bh & 15;
    int q0 = blockIdx.x * 64;
    int tb = b * S_LEN;
    int tid = threadIdx.x;
    int ty = tid / 16, tx = tid % 16;

    for (int i = tid; i < 64 * 32; i += 256) {
        int r = i >> 5, c4 = (i & 31) * 4;
        float4 v = *(const float4*)(g_Q + (size_t)(tb + q0 + r) * 2048 + h * 128 + c4);
        Qs[r * 129 + c4] = v.x; Qs[r * 129 + c4 + 1] = v.y;
        Qs[r * 129 + c4 + 2] = v.z; Qs[r * 129 + c4 + 3] = v.w;
    }
    if (tid < 64) { mrow[tid] = -1e30f; lrow[tid] = 0.f; }
    float acc[4][8];
    #pragma unroll
    for (int i = 0; i < 4; i++)
        #pragma unroll
        for (int j = 0; j < 8; j++) acc[i][j] = 0.f;
    const float scale = 1.0f / sqrtf(192.0f);
    __syncthreads();

    int nkt = blockIdx.x + 1;
    for (int kt = 0; kt < nkt; kt++) {
        int k0 = kt * 64;
        for (int i = tid; i < 64 * 32; i += 256) {
            int r = i >> 5, c4 = (i & 31) * 4;
            const float* kp = g_KV + (size_t)(tb + k0 + r) * 4096 + h * 128;
            float4 kv4 = *(const float4*)(kp + c4);
            Ks[r * 129 + c4] = kv4.x; Ks[r * 129 + c4 + 1] = kv4.y;
            Ks[r * 129 + c4 + 2] = kv4.z; Ks[r * 129 + c4 + 3] = kv4.w;
            float4 vv4 = *(const float4*)(kp + 2048 + c4);
            Vs[r * 132 + c4] = vv4.x; Vs[r * 132 + c4 + 1] = vv4.y;
            Vs[r * 132 + c4 + 2] = vv4.z; Vs[r * 132 + c4 + 3] = vv4.w;
        }
        __syncthreads();
        float s[4][4];
        #pragma unroll
        for (int i = 0; i < 4; i++)
            #pragma unroll
            for (int j = 0; j < 4; j++) s[i][j] = 0.f;
        #pragma unroll 4
        for (int k = 0; k < 128; k++) {
            float qa[4], kb[4];
            #pragma unroll
            for (int i = 0; i < 4; i++) qa[i] = Qs[(4 * ty + i) * 129 + k];
            #pragma unroll
            for (int j = 0; j < 4; j++) kb[j] = Ks[(4 * tx + j) * 129 + k];
            #pragma unroll
            for (int i = 0; i < 4; i++)
                #pragma unroll
                for (int j = 0; j < 4; j++) s[i][j] += qa[i] * kb[j];
        }
        #pragma unroll
        for (int i = 0; i < 4; i++)
            #pragma unroll
            for (int j = 0; j < 4; j++) {
                int rq = q0 + 4 * ty + i, ck = k0 + 4 * tx + j;
                Ps[(4 * ty + i) * 65 + 4 * tx + j] = (ck <= rq) ? s[i][j] * scale : -1e30f;
            }
        __syncthreads();
        if (tid < 64) {
            float m0 = mrow[tid], mx = m0;
            for (int c = 0; c < 64; c++) mx = fmaxf(mx, Ps[tid * 65 + c]);
            float cr = __expf(m0 - mx);
            float l = lrow[tid] * cr;
            for (int c = 0; c < 64; c++) {
                float p = __expf(Ps[tid * 65 + c] - mx);
                Ps[tid * 65 + c] = p; l += p;
            }
            mrow[tid] = mx; lrow[tid] = l; corr[tid] = cr;
        }
        __syncthreads();
        #pragma unroll
        for (int i = 0; i < 4; i++) {
            float cr = corr[4 * ty + i];
            #pragma unroll
            for (int j = 0; j < 8; j++) acc[i][j] *= cr;
        }
        #pragma unroll 2
        for (int c = 0; c < 64; c++) {
            float p[4], v[8];
            #pragma unroll
            for (int i = 0; i < 4; i++) p[i] = Ps[(4 * ty + i) * 65 + c];
            #pragma unroll
            for (int j = 0; j < 8; j++) v[j] = Vs[c * 132 + 8 * tx + j];
            #pragma unroll
            for (int i = 0; i < 4; i++)
                #pragma unroll
                for (int j = 0; j < 8; j++) acc[i][j] += p[i] * v[j];
        }
        __syncthreads();
    }
    #pragma unroll
    for (int i = 0; i < 4; i++) {
        int r = 4 * ty + i;
        float inv = 1.0f / lrow[r];
        #pragma unroll
        for (int j = 0; j < 8; j++)
            g_attn[(size_t)(tb + q0 + r) * 2048 + h * 128 + 8 * tx + j] = acc[i][j] * inv;
    }
}

// ---------------- gate ----------------
__global__ void __launch_bounds__(512) zero_cnt() { if (threadIdx.x < E_NUM) g_cnt[threadIdx.x] = 0; }

__global__ void __launch_bounds__(512) gate_kernel(const float* __restrict__ gate_w) {
    int t = blockIdx.x;
    int w = threadIdx.x >> 5, lane = threadIdx.x & 31;
    const float* x = g_X2 + (size_t)t * H_DIM;
    const float* gw = gate_w + (size_t)w * H_DIM;
    float s = 0.f;
    for (int i = lane; i < H_DIM; i += 32) s += x[i] * gw[i];
    #pragma unroll
    for (int o = 16; o; o >>= 1) s += __shfl_xor_sync(0xffffffffu, s, o);
    __shared__ float lg[E_NUM];
    if (lane == 0) lg[w] = s;
    __syncthreads();
    if (threadIdx.x == 0) {
        float mx = -1e30f;
        for (int e = 0; e < E_NUM; e++) mx = fmaxf(mx, lg[e]);
        float pe[E_NUM];
        for (int e = 0; e < E_NUM; e++) pe[e] = expf(lg[e] - mx);
        bool used[E_NUM];
        for (int e = 0; e < E_NUM; e++) used[e] = false;
        int sel[4]; float sw[4]; float wsum = 0.f;
        for (int j = 0; j < 4; j++) {
            int bi = -1; float bv = -1.f;
            for (int e = 0; e < E_NUM; e++)
                if (!used[e] && pe[e] > bv) { bv = pe[e]; bi = e; }
            used[bi] = true; sel[j] = bi; sw[j] = bv; wsum += bv;
        }
        for (int j = 0; j < 4; j++) {
            int e = sel[j];
            int pos = atomicAdd(&g_cnt[e], 1);
            g_tok[e * T_TOK + pos] = t;
            g_texp[t * 4 + j] = e;
            g_trow[t * 4 + j] = pos;
            g_twt [t * 4 + j] = sw[j] / wsum;
        }
    }
}

// ---------------- activations ----------------
__device__ __forceinline__ float silu_f(float x) { return x / (1.0f + __expf(-x)); }

__global__ void __launch_bounds__(256) act_moe() {
    int e = blockIdx.y;
    int r = blockIdx.x;
    if (r >= g_cnt[e]) return;
    float* row = g_gu + ((size_t)e * T_TOK + r) * TWO_I;
    for (int i = threadIdx.x; i < I_DIM; i += 256) {
        float g = row[i], u = row[I_DIM + i];
        row[i] = silu_f(g) * u;
    }
}

__global__ void __launch_bounds__(256) act_shared() {
    int t = blockIdx.x;
    float* row = g_sgu + (size_t)t * SH2;
    for (int i = threadIdx.x; i < SHI_DIM; i += 256) {
        float g = row[i], u = row[SHI_DIM + i];
        row[i] = silu_f(g) * u;
    }
}

// ---------------- final sum ----------------
__global__ void __launch_bounds__(256) final_sum(float* __restrict__ out) {
    int t = blockIdx.x;
    int e0 = g_texp[t * 4 + 0], e1 = g_texp[t * 4 + 1], e2 = g_texp[t * 4 + 2], e3 = g_texp[t * 4 + 3];
    int r0 = g_trow[t * 4 + 0], r1 = g_trow[t * 4 + 1], r2 = g_trow[t * 4 + 2], r3 = g_trow[t * 4 + 3];
    float w0 = g_twt[t * 4 + 0], w1v = g_twt[t * 4 + 1], w2v = g_twt[t * 4 + 2], w3 = g_twt[t * 4 + 3];
    const float* d0 = g_down + ((size_t)e0 * T_TOK + r0) * H_DIM;
    const float* d1 = g_down + ((size_t)e1 * T_TOK + r1) * H_DIM;
    const float* d2 = g_down + ((size_t)e2 * T_TOK + r2) * H_DIM;
    const float* d3 = g_down + ((size_t)e3 * T_TOK + r3) * H_DIM;
    for (int h = threadIdx.x; h < H_DIM; h += 256) {
        float v = out[(size_t)t * H_DIM + h];
        v += w0 * d0[h] + w1v * d1[h] + w2v * d2[h] + w3 * d3[h];
        out[(size_t)t * H_DIM + h] = v;
    }
}

// ---------------- launch ----------------
extern "C" void kernel_launch(void* const* d_in, const int* in_sizes, int n_in,
                              void* d_out, int out_size) {
    (void)in_sizes; (void)n_in; (void)out_size;
    const float* hidden  = (const float*)d_in[0];
    const float* ln1_w   = (const float*)d_in[2];
    const float* ln2_w   = (const float*)d_in[3];
    const float* q_w     = (const float*)d_in[4];
    const float* kv_w    = (const float*)d_in[5];
    const float* o_w     = (const float*)d_in[6];
    const float* gate_w  = (const float*)d_in[7];
    const float* w1      = (const float*)d_in[8];
    const float* w2      = (const float*)d_in[9];
    const float* sh_gu_w = (const float*)d_in[10];
    const float* sh_dn_w = (const float*)d_in[11];
    float* out = (float*)d_out;

    float *pX, *pQ, *pKV, *pAttn, *pHid, *pX2, *pSgu, *pGu, *pDown;
    cudaGetSymbolAddress((void**)&pX, g_X);
    cudaGetSymbolAddress((void**)&pQ, g_Q);
    cudaGetSymbolAddress((void**)&pKV, g_KV);
    cudaGetSymbolAddress((void**)&pAttn, g_attn);
    cudaGetSymbolAddress((void**)&pHid, g_hid);
    cudaGetSymbolAddress((void**)&pX2, g_X2);
    cudaGetSymbolAddress((void**)&pSgu, g_sgu);
    cudaGetSymbolAddress((void**)&pGu, g_gu);
    cudaGetSymbolAddress((void**)&pDown, g_down);

    const int ATTN_SMEM = (64 * 129 + 64 * 129 + 64 * 132 + 64 * 65 + 192) * 4;
    cudaFuncSetAttribute(attn_kernel, cudaFuncAttributeMaxDynamicSharedMemorySize, ATTN_SMEM);
    cudaFuncSetAttribute(gemm_mma<0, true,  false>, cudaFuncAttributeMaxDynamicSharedMemorySize, GSMEM_BYTES);
    cudaFuncSetAttribute(gemm_mma<0, false, false>, cudaFuncAttributeMaxDynamicSharedMemorySize, GSMEM_BYTES);
    cudaFuncSetAttribute(gemm_mma<0, false, true >, cudaFuncAttributeMaxDynamicSharedMemorySize, GSMEM_BYTES);
    cudaFuncSetAttribute(gemm_mma<1, false, false>, cudaFuncAttributeMaxDynamicSharedMemorySize, GSMEM_BYTES);
    cudaFuncSetAttribute(gemm_mma<2, false, false>, cudaFuncAttributeMaxDynamicSharedMemorySize, GSMEM_BYTES);

    // 1) x = rmsnorm(hidden, ln1_w)
    rmsnorm_kernel<<<T_TOK, 256>>>(hidden, ln1_w, pX);
    // 2) Q (nope rows only, via q_w row map)
    gemm_mma<0, true, false><<<dim3(16, 16, 1), 256, GSMEM_BYTES>>>(
        pX, 0LL, H_DIM, q_w, 0LL, H_DIM, pQ, 0LL, 2048, T_TOK, H_DIM, nullptr, 0);
    // 3) KV (first 4096 rows of kv_w)
    gemm_mma<0, false, false><<<dim3(32, 16, 1), 256, GSMEM_BYTES>>>(
        pX, 0LL, H_DIM, kv_w, 0LL, H_DIM, pKV, 0LL, 4096, T_TOK, H_DIM, nullptr, 0);
    // 4) causal flash attention
    attn_kernel<<<dim3(16, 32), 256, ATTN_SMEM>>>();
    // 5) hid = attn @ o_w^T + hidden
    gemm_mma<0, false, true><<<dim3(16, 16, 1), 256, GSMEM_BYTES>>>(
        pAttn, 0LL, 2048, o_w, 0LL, 2048, pHid, 0LL, H_DIM, T_TOK, 2048, hidden, H_DIM);
    // 6) x2 = rmsnorm(hid, ln2_w)
    rmsnorm_kernel<<<T_TOK, 256>>>(pHid, ln2_w, pX2);
    // 7) routing
    zero_cnt<<<1, 32>>>();
    gate_kernel<<<T_TOK, 512>>>(gate_w);
    // 8) routed GU (top-4, gathered per expert)
    gemm_mma<1, false, false><<<dim3(22, 16, E_NUM), 256, GSMEM_BYTES>>>(
        pX2, 0LL, H_DIM,
        w1, (long long)TWO_I * H_DIM, H_DIM,
        pGu, (long long)T_TOK * TWO_I, TWO_I,
        0, H_DIM, nullptr, 0);
    // 9) routed act
    act_moe<<<dim3(T_TOK, E_NUM), 256>>>();
    // 10) routed down
    gemm_mma<2, false, false><<<dim3(16, 16, E_NUM), 256, GSMEM_BYTES>>>(
        pGu, (long long)T_TOK * TWO_I, TWO_I,
        w2, (long long)H_DIM * I_DIM, I_DIM,
        pDown, (long long)T_TOK * H_DIM, H_DIM,
        0, I_DIM, nullptr, 0);
    // 11) shared GU
    gemm_mma<0, false, false><<<dim3(44, 16, 1), 256, GSMEM_BYTES>>>(
        pX2, 0LL, H_DIM, sh_gu_w, 0LL, H_DIM, pSgu, 0LL, SH2, T_TOK, H_DIM, nullptr, 0);
    // 12) shared act
    act_shared<<<T_TOK, 256>>>();
    // 13) out = act @ sh_dn^T + hid
    gemm_mma<0, false, true><<<dim3(16, 16, 1), 256, GSMEM_BYTES>>>(
        pSgu, 0LL, SH2, sh_dn_w, 0LL, SHI_DIM, out, 0LL, H_DIM, T_TOK, SHI_DIM, pHid, H_DIM);
    // 14) out += weighted routed contributions
    final_sum<<<T_TOK, 256>>>(out);
}

// round 4
// speedup vs baseline: 2.1530x; 1.0247x over previous
#include <cuda_runtime.h>
#include <cuda_bf16.h>
#include <cstdint>
#include <math.h>

#define T_TOK 2048
#define H_DIM 2048
#define S_LEN 1024
#define NHEAD 16
#define E_NUM 16
#define I_DIM 1408
#define TWO_I 2816
#define SHI_DIM 2816
#define SH2 5632

// ---------------- fp32 scratch ----------------
__device__ float g_X   [(size_t)T_TOK * H_DIM];
__device__ float g_Q   [(size_t)T_TOK * 2048];
__device__ float g_KV  [(size_t)T_TOK * 4096];
__device__ float g_hid [(size_t)T_TOK * H_DIM];
__device__ float g_X2  [(size_t)T_TOK * H_DIM];
__device__ float g_sgu [(size_t)T_TOK * SH2];
__device__ float g_gu  [(size_t)E_NUM * T_TOK * TWO_I];
__device__ float g_down[(size_t)E_NUM * T_TOK * H_DIM];
__device__ int   g_cnt [E_NUM];
__device__ int   g_tok [E_NUM * T_TOK];
__device__ int   g_texp[T_TOK * 4];
__device__ int   g_trow[T_TOK * 4];
__device__ float g_twt [T_TOK * 4];

// ---------------- bf16 hi/lo planes ----------------
__device__ __nv_bfloat16 c_Xhi [(size_t)T_TOK * H_DIM],      c_Xlo [(size_t)T_TOK * H_DIM];
__device__ __nv_bfloat16 c_athi[(size_t)T_TOK * 2048],       c_atlo[(size_t)T_TOK * 2048];
__device__ __nv_bfloat16 c_X2hi[(size_t)T_TOK * H_DIM],      c_X2lo[(size_t)T_TOK * H_DIM];
__device__ __nv_bfloat16 c_guhi[(size_t)E_NUM * T_TOK * I_DIM], c_gulo[(size_t)E_NUM * T_TOK * I_DIM];
__device__ __nv_bfloat16 c_sahi[(size_t)T_TOK * SHI_DIM],    c_salo[(size_t)T_TOK * SHI_DIM];
__device__ __nv_bfloat16 c_qwhi[(size_t)2048 * 2048],        c_qwlo[(size_t)2048 * 2048];
__device__ __nv_bfloat16 c_kvhi[(size_t)4096 * 2048],        c_kvlo[(size_t)4096 * 2048];
__device__ __nv_bfloat16 c_owhi[(size_t)2048 * 2048],        c_owlo[(size_t)2048 * 2048];
__device__ __nv_bfloat16 c_w1hi[(size_t)E_NUM * TWO_I * H_DIM], c_w1lo[(size_t)E_NUM * TWO_I * H_DIM];
__device__ __nv_bfloat16 c_w2hi[(size_t)E_NUM * H_DIM * I_DIM], c_w2lo[(size_t)E_NUM * H_DIM * I_DIM];
__device__ __nv_bfloat16 c_sghi[(size_t)SH2 * H_DIM],        c_sglo[(size_t)SH2 * H_DIM];
__device__ __nv_bfloat16 c_sdhi[(size_t)H_DIM * SHI_DIM],    c_sdlo[(size_t)H_DIM * SHI_DIM];

// ================= helpers =================
static __device__ __forceinline__ uint32_t smem_u32(const void* p) {
    uint32_t a;
    asm("{ .reg .u64 t; cvta.to.shared.u64 t, %1; cvt.u32.u64 %0, t; }" : "=r"(a) : "l"(p));
    return a;
}
static __device__ __forceinline__ uint32_t hi2(float x, float y) {
    uint32_t r;
    asm("prmt.b32 %0, %1, %2, 0x7632;" : "=r"(r) : "r"(__float_as_uint(x)), "r"(__float_as_uint(y)));
    return r;
}
static __device__ __forceinline__ uint32_t lo2(float x, float y, uint32_t h) {
    float hx = __uint_as_float(h << 16);
    float hy = __uint_as_float(h & 0xffff0000u);
    float lx = x - hx, ly = y - hy;
    uint32_t r;
    asm("cvt.rn.bf16x2.f32 %0, %1, %2;" : "=r"(r) : "f"(ly), "f"(lx));
    return r;
}
#define LDM4(r, a) \
    asm volatile("ldmatrix.sync.aligned.m8n8.x4.shared.b16 {%0,%1,%2,%3}, [%4];" \
        : "=r"((r)[0]), "=r"((r)[1]), "=r"((r)[2]), "=r"((r)[3]) : "r"(a))
#define MMA16816(c, a, b0, b1) \
    asm volatile("mma.sync.aligned.m16n8k16.row.col.f32.bf16.bf16.f32 " \
        "{%0,%1,%2,%3}, {%4,%5,%6,%7}, {%8,%9}, {%0,%1,%2,%3};" \
        : "+f"((c)[0]), "+f"((c)[1]), "+f"((c)[2]), "+f"((c)[3]) \
        : "r"((a)[0]), "r"((a)[1]), "r"((a)[2]), "r"((a)[3]), "r"(b0), "r"(b1))
#define CPA16(d, s, n) \
    asm volatile("cp.async.cg.shared.global [%0], [%1], 16, %2;" :: "r"(d), "l"(s), "r"(n) : "memory")
#define CPA_COMMIT() asm volatile("cp.async.commit_group;" ::: "memory")
#define CPA_WAIT2()  asm volatile("cp.async.wait_group 2;" ::: "memory")

// ================= conversion kernels =================
__global__ void __launch_bounds__(256) conv_gen(const float* __restrict__ src,
                                                __nv_bfloat16* __restrict__ dhi,
                                                __nv_bfloat16* __restrict__ dlo,
                                                long long n4) {
    long long stride = (long long)gridDim.x * 256;
    for (long long i = (long long)blockIdx.x * 256 + threadIdx.x; i < n4; i += stride) {
        float4 v = ((const float4*)src)[i];
        uint32_t h0 = hi2(v.x, v.y), h1 = hi2(v.z, v.w);
        uint32_t l0 = lo2(v.x, v.y, h0), l1 = lo2(v.z, v.w, h1);
        ((uint2*)dhi)[i] = make_uint2(h0, h1);
        ((uint2*)dlo)[i] = make_uint2(l0, l1);
    }
}
// q_w: out row n (0..2047) <- src row (n>>7)*192 + (n&127)
__global__ void __launch_bounds__(256) conv_qw(const float* __restrict__ src) {
    long long n4 = (long long)2048 * 512;
    long long stride = (long long)gridDim.x * 256;
    for (long long i = (long long)blockIdx.x * 256 + threadIdx.x; i < n4; i += stride) {
        int row = (int)(i >> 9), c4 = (int)(i & 511);
        int sr = (row >> 7) * 192 + (row & 127);
        float4 v = ((const float4*)(src + (long long)sr * 2048))[c4];
        uint32_t h0 = hi2(v.x, v.y), h1 = hi2(v.z, v.w);
        uint32_t l0 = lo2(v.x, v.y, h0), l1 = lo2(v.z, v.w, h1);
        ((uint2*)c_qwhi)[i] = make_uint2(h0, h1);
        ((uint2*)c_qwlo)[i] = make_uint2(l0, l1);
    }
}

// ================= cp.async HMMA bf16x3 GEMM =================
// C[M,N] = A @ W^T (+addsrc). 128x128 tile, BK=32, 8 warps, 4-stage cp.async ring.
// Stage layout: Ahi[128x80B] Alo Bhi Blo (10240B each); stage=40960B; 4 stages=160KB.
// MODE: 0 plain (M arg), 1 gather A rows via g_tok (M=g_cnt[e]), 2 grouped A base (M=g_cnt[e]).
#define GSMEM_BYTES (4 * 40960)

template <int MODE, bool ADD>
__global__ void __launch_bounds__(256, 1) gemm_cp(
    const __nv_bfloat16* __restrict__ Ahi, const __nv_bfloat16* __restrict__ Alo,
    long long aestride, int lda,
    const __nv_bfloat16* __restrict__ Bhi, const __nv_bfloat16* __restrict__ Blo,
    long long bestride,
    float* __restrict__ C, long long cstride, int ldc,
    int M, int K,
    const float* __restrict__ addsrc, int ldadd)
{
    extern __shared__ char smem[];
    const int e  = blockIdx.z;
    const int Me = (MODE == 0) ? M : g_cnt[e];
    const int bm = blockIdx.y * 128, bn = blockIdx.x * 128;
    if (bm >= Me) return;
    const __nv_bfloat16* AhiB = Ahi + (MODE == 2 ? (long long)e * aestride : 0LL);
    const __nv_bfloat16* AloB = Alo + (MODE == 2 ? (long long)e * aestride : 0LL);
    const __nv_bfloat16* BhiB = Bhi + (long long)e * bestride;
    const __nv_bfloat16* BloB = Blo + (long long)e * bestride;
    float* Cb = C + (long long)e * cstride;

    const uint32_t sb = smem_u32(smem);
    const int tid = threadIdx.x, wid = tid >> 5, lid = tid & 31;
    const int wm = wid & 3, wn = wid >> 2;

    // staging: q = tid, tid+256 -> row=q>>2, seg=q&3 (16B each)
    uint32_t sOff[2]; uint32_t aval[2];
    const char *aHp[2], *aLp[2], *bHp[2], *bLp[2];
    #pragma unroll
    for (int i = 0; i < 2; i++) {
        int q = tid + i * 256;
        int row = q >> 2, seg = q & 3;
        sOff[i] = (uint32_t)(row * 80 + seg * 16);
        int gm = bm + row;
        aval[i] = (gm < Me) ? 16u : 0u;
        long long arow;
        if (MODE == 1) arow = (gm < Me) ? (long long)g_tok[e * T_TOK + gm] : 0LL;
        else           arow = (gm < Me) ? (long long)gm : 0LL;
        aHp[i] = (const char*)(AhiB + arow * (long long)lda) + seg * 16;
        aLp[i] = (const char*)(AloB + arow * (long long)lda) + seg * 16;
        long long brow = (long long)(bn + row);
        bHp[i] = (const char*)(BhiB + brow * (long long)lda) + seg * 16;
        bLp[i] = (const char*)(BloB + brow * (long long)lda) + seg * 16;
    }

    // ldmatrix fragment offsets
    const int laneRow = lid & 15, laneChk = lid >> 4;
    uint32_t aOff[2], bOff[4];
    #pragma unroll
    for (int t = 0; t < 2; t++)
        aOff[t] = (uint32_t)((wm * 32 + t * 16 + laneRow) * 80 + laneChk * 16);
    #pragma unroll
    for (int p = 0; p < 4; p++)
        bOff[p] = (uint32_t)(20480 + (wn * 64 + p * 16 + laneRow) * 80 + laneChk * 16);

    float acc[2][8][4];
    #pragma unroll
    for (int t = 0; t < 2; t++)
        #pragma unroll
        for (int n8 = 0; n8 < 8; n8++)
            #pragma unroll
            for (int j = 0; j < 4; j++) acc[t][n8][j] = 0.f;

    const int NC = K / 32;

    // issue chunk c into stage c&3
    #define ISSUE(c) do { \
        uint32_t st_ = sb + (uint32_t)((c) & 3) * 40960u; \
        long long kb_ = (long long)(c) * 64; \
        _Pragma("unroll") \
        for (int i_ = 0; i_ < 2; i_++) { \
            CPA16(st_ + sOff[i_],          aHp[i_] + kb_, aval[i_]); \
            CPA16(st_ + 10240u + sOff[i_], aLp[i_] + kb_, aval[i_]); \
            CPA16(st_ + 20480u + sOff[i_], bHp[i_] + kb_, 16u); \
            CPA16(st_ + 30720u + sOff[i_], bLp[i_] + kb_, 16u); \
        } \
    } while (0)

    ISSUE(0); CPA_COMMIT();
    if (NC > 1) { ISSUE(1); } CPA_COMMIT();
    if (NC > 2) { ISSUE(2); } CPA_COMMIT();

    for (int c = 0; c < NC; c++) {
        CPA_WAIT2();
        __syncthreads();
        const uint32_t stg = sb + (uint32_t)(c & 3) * 40960u;
        #pragma unroll
        for (int h = 0; h < 2; h++) {
            uint32_t ah0[4], ah1[4], al0[4], al1[4];
            LDM4(ah0, stg + aOff[0] + h * 32);
            LDM4(ah1, stg + aOff[1] + h * 32);
            LDM4(al0, stg + aOff[0] + 10240u + h * 32);
            LDM4(al1, stg + aOff[1] + 10240u + h * 32);
            #pragma unroll
            for (int p = 0; p < 4; p++) {
                uint32_t bh[4], bl[4];
                LDM4(bh, stg + bOff[p] + h * 32);
                MMA16816(acc[0][2 * p],     ah0, bh[0], bh[2]);
                MMA16816(acc[0][2 * p + 1], ah0, bh[1], bh[3]);
                MMA16816(acc[1][2 * p],     ah1, bh[0], bh[2]);
                MMA16816(acc[1][2 * p + 1], ah1, bh[1], bh[3]);
                MMA16816(acc[0][2 * p],     al0, bh[0], bh[2]);
                MMA16816(acc[0][2 * p + 1], al0, bh[1], bh[3]);
                MMA16816(acc[1][2 * p],     al1, bh[0], bh[2]);
                MMA16816(acc[1][2 * p + 1], al1, bh[1], bh[3]);
                LDM4(bl, stg + bOff[p] + 10240u + h * 32);
                MMA16816(acc[0][2 * p],     ah0, bl[0], bl[2]);
                MMA16816(acc[0][2 * p + 1], ah0, bl[1], bl[3]);
                MMA16816(acc[1][2 * p],     ah1, bl[0], bl[2]);
                MMA16816(acc[1][2 * p + 1], ah1, bl[1], bl[3]);
            }
        }
        __syncthreads();
        if (c + 3 < NC) ISSUE(c + 3);
        CPA_COMMIT();
    }
    #undef ISSUE

    // epilogue
    const int g = lid >> 2, tg = lid & 3;
    #pragma unroll
    for (int t = 0; t < 2; t++) {
        #pragma unroll
        for (int half = 0; half < 2; half++) {
            int row = bm + wm * 32 + t * 16 + g + half * 8;
            if (row >= Me) continue;
            float* cp = Cb + (long long)row * ldc + bn + wn * 64 + tg * 2;
            const float* ap = ADD ? (addsrc + (long long)row * ldadd + bn + wn * 64 + tg * 2) : (const float*)0;
            #pragma unroll
            for (int n8 = 0; n8 < 8; n8++) {
                float v0 = acc[t][n8][half * 2], v1 = acc[t][n8][half * 2 + 1];
                if (ADD) { v0 += ap[n8 * 8]; v1 += ap[n8 * 8 + 1]; }
                cp[n8 * 8] = v0; cp[n8 * 8 + 1] = v1;
            }
        }
    }
}

// ---------------- rmsnorm (fp32 out + hi/lo planes) ----------------
__global__ __launch_bounds__(256) void rmsnorm_kernel(const float* __restrict__ in,
                                                      const float* __restrict__ w,
                                                      float* __restrict__ out,
                                                      __nv_bfloat16* __restrict__ phi,
                                                      __nv_bfloat16* __restrict__ plo) {
    int t = blockIdx.x;
    const float* row = in + (size_t)t * H_DIM;
    float ss = 0.f;
    for (int i = threadIdx.x; i < H_DIM; i += 256) { float v = row[i]; ss += v * v; }
    __shared__ float red[8];
    #pragma unroll
    for (int o = 16; o; o >>= 1) ss += __shfl_xor_sync(0xffffffffu, ss, o);
    if ((threadIdx.x & 31) == 0) red[threadIdx.x >> 5] = ss;
    __syncthreads();
    if (threadIdx.x < 32) {
        float v = (threadIdx.x < 8) ? red[threadIdx.x] : 0.f;
        #pragma unroll
        for (int o = 4; o; o >>= 1) v += __shfl_xor_sync(0xffffffffu, v, o);
        if (threadIdx.x == 0) red[0] = v;
    }
    __syncthreads();
    float inv = rsqrtf(red[0] * (1.0f / H_DIM) + 1e-6f);
    for (int i = threadIdx.x * 2; i < H_DIM; i += 512) {
        float a = row[i] * inv * w[i];
        float b = row[i + 1] * inv * w[i + 1];
        out[(size_t)t * H_DIM + i] = a;
        out[(size_t)t * H_DIM + i + 1] = b;
        uint32_t h = hi2(a, b), l = lo2(a, b, h);
        ((uint32_t*)phi)[((size_t)t * H_DIM + i) >> 1] = h;
        ((uint32_t*)plo)[((size_t)t * H_DIM + i) >> 1] = l;
    }
}

// ---------------- flash attention (fp32, causal, D=128; writes bf16 planes) ----------------
__global__ void __launch_bounds__(256) attn_kernel() {
    extern __shared__ float sm[];
    float* Qs = sm;
    float* Ks = Qs + 64 * 129;
    float* Vs = Ks + 64 * 129;
    float* Ps = Vs + 64 * 132;
    float* mrow = Ps + 64 * 65;
    float* lrow = mrow + 64;
    float* corr = lrow + 64;

    int bh = blockIdx.y; int b = bh >> 4, h = bh & 15;
    int q0 = blockIdx.x * 64;
    int tb = b * S_LEN;
    int tid = threadIdx.x;
    int ty = tid / 16, tx = tid % 16;

    for (int i = tid; i < 64 * 32; i += 256) {
        int r = i >> 5, c4 = (i & 31) * 4;
        float4 v = *(const float4*)(g_Q + (size_t)(tb + q0 + r) * 2048 + h * 128 + c4);
        Qs[r * 129 + c4] = v.x; Qs[r * 129 + c4 + 1] = v.y;
        Qs[r * 129 + c4 + 2] = v.z; Qs[r * 129 + c4 + 3] = v.w;
    }
    if (tid < 64) { mrow[tid] = -1e30f; lrow[tid] = 0.f; }
    float acc[4][8];
    #pragma unroll
    for (int i = 0; i < 4; i++)
        #pragma unroll
        for (int j = 0; j < 8; j++) acc[i][j] = 0.f;
    const float scale = 1.0f / sqrtf(192.0f);
    __syncthreads();

    int nkt = blockIdx.x + 1;
    for (int kt = 0; kt < nkt; kt++) {
        int k0 = kt * 64;
        for (int i = tid; i < 64 * 32; i += 256) {
            int r = i >> 5, c4 = (i & 31) * 4;
            const float* kp = g_KV + (size_t)(tb + k0 + r) * 4096 + h * 128;
            float4 kv4 = *(const float4*)(kp + c4);
            Ks[r * 129 + c4] = kv4.x; Ks[r * 129 + c4 + 1] = kv4.y;
            Ks[r * 129 + c4 + 2] = kv4.z; Ks[r * 129 + c4 + 3] = kv4.w;
            float4 vv4 = *(const float4*)(kp + 2048 + c4);
            Vs[r * 132 + c4] = vv4.x; Vs[r * 132 + c4 + 1] = vv4.y;
            Vs[r * 132 + c4 + 2] = vv4.z; Vs[r * 132 + c4 + 3] = vv4.w;
        }
        __syncthreads();
        float s[4][4];
        #pragma unroll
        for (int i = 0; i < 4; i++)
            #pragma unroll
            for (int j = 0; j < 4; j++) s[i][j] = 0.f;
        #pragma unroll 4
        for (int k = 0; k < 128; k++) {
            float qa[4], kb[4];
            #pragma unroll
            for (int i = 0; i < 4; i++) qa[i] = Qs[(4 * ty + i) * 129 + k];
            #pragma unroll
            for (int j = 0; j < 4; j++) kb[j] = Ks[(4 * tx + j) * 129 + k];
            #pragma unroll
            for (int i = 0; i < 4; i++)
                #pragma unroll
                for (int j = 0; j < 4; j++) s[i][j] += qa[i] * kb[j];
        }
        #pragma unroll
        for (int i = 0; i < 4; i++)
            #pragma unroll
            for (int j = 0; j < 4; j++) {
                int rq = q0 + 4 * ty + i, ck = k0 + 4 * tx + j;
                Ps[(4 * ty + i) * 65 + 4 * tx + j] = (ck <= rq) ? s[i][j] * scale : -1e30f;
            }
        __syncthreads();
        if (tid < 64) {
            float m0 = mrow[tid], mx = m0;
            for (int c = 0; c < 64; c++) mx = fmaxf(mx, Ps[tid * 65 + c]);
            float cr = __expf(m0 - mx);
            float l = lrow[tid] * cr;
            for (int c = 0; c < 64; c++) {
                float p = __expf(Ps[tid * 65 + c] - mx);
                Ps[tid * 65 + c] = p; l += p;
            }
            mrow[tid] = mx; lrow[tid] = l; corr[tid] = cr;
        }
        __syncthreads();
        #pragma unroll
        for (int i = 0; i < 4; i++) {
            float cr = corr[4 * ty + i];
            #pragma unroll
            for (int j = 0; j < 8; j++) acc[i][j] *= cr;
        }
        #pragma unroll 2
        for (int c = 0; c < 64; c++) {
            float p[4], v[8];
            #pragma unroll
            for (int i = 0; i < 4; i++) p[i] = Ps[(4 * ty + i) * 65 + c];
            #pragma unroll
            for (int j = 0; j < 8; j++) v[j] = Vs[c * 132 + 8 * tx + j];
            #pragma unroll
            for (int i = 0; i < 4; i++)
                #pragma unroll
                for (int j = 0; j < 8; j++) acc[i][j] += p[i] * v[j];
        }
        __syncthreads();
    }
    #pragma unroll
    for (int i = 0; i < 4; i++) {
        int r = 4 * ty + i;
        float inv = 1.0f / lrow[r];
        float v[8];
        #pragma unroll
        for (int j = 0; j < 8; j++) v[j] = acc[i][j] * inv;
        size_t base = (size_t)(tb + q0 + r) * 2048 + h * 128 + 8 * tx;
        uint32_t h0 = hi2(v[0], v[1]), h1 = hi2(v[2], v[3]), h2 = hi2(v[4], v[5]), h3 = hi2(v[6], v[7]);
        uint32_t l0 = lo2(v[0], v[1], h0), l1 = lo2(v[2], v[3], h1);
        uint32_t l2 = lo2(v[4], v[5], h2), l3 = lo2(v[6], v[7], h3);
        *(uint2*)(c_athi + base)     = make_uint2(h0, h1);
        *(uint2*)(c_athi + base + 4) = make_uint2(h2, h3);
        *(uint2*)(c_atlo + base)     = make_uint2(l0, l1);
        *(uint2*)(c_atlo + base + 4) = make_uint2(l2, l3);
    }
}

// ---------------- gate ----------------
__global__ void __launch_bounds__(512) zero_cnt() { if (threadIdx.x < E_NUM) g_cnt[threadIdx.x] = 0; }

__global__ void __launch_bounds__(512) gate_kernel(const float* __restrict__ gate_w) {
    int t = blockIdx.x;
    int w = threadIdx.x >> 5, lane = threadIdx.x & 31;
    const float* x = g_X2 + (size_t)t * H_DIM;
    const float* gw = gate_w + (size_t)w * H_DIM;
    float s = 0.f;
    for (int i = lane; i < H_DIM; i += 32) s += x[i] * gw[i];
    #pragma unroll
    for (int o = 16; o; o >>= 1) s += __shfl_xor_sync(0xffffffffu, s, o);
    __shared__ float lg[E_NUM];
    if (lane == 0) lg[w] = s;
    __syncthreads();
    if (threadIdx.x == 0) {
        float mx = -1e30f;
        for (int e = 0; e < E_NUM; e++) mx = fmaxf(mx, lg[e]);
        float pe[E_NUM];
        for (int e = 0; e < E_NUM; e++) pe[e] = expf(lg[e] - mx);
        bool used[E_NUM];
        for (int e = 0; e < E_NUM; e++) used[e] = false;
        int sel[4]; float sw[4]; float wsum = 0.f;
        for (int j = 0; j < 4; j++) {
            int bi = -1; float bv = -1.f;
            for (int e = 0; e < E_NUM; e++)
                if (!used[e] && pe[e] > bv) { bv = pe[e]; bi = e; }
            used[bi] = true; sel[j] = bi; sw[j] = bv; wsum += bv;
        }
        for (int j = 0; j < 4; j++) {
            int e = sel[j];
            int pos = atomicAdd(&g_cnt[e], 1);
            g_tok[e * T_TOK + pos] = t;
            g_texp[t * 4 + j] = e;
            g_trow[t * 4 + j] = pos;
            g_twt [t * 4 + j] = sw[j] / wsum;
        }
    }
}

// ---------------- activations (write bf16 planes) ----------------
__device__ __forceinline__ float silu_f(float x) { return x / (1.0f + __expf(-x)); }

__global__ void __launch_bounds__(256) act_moe() {
    int e = blockIdx.y;
    int r = blockIdx.x;
    if (r >= g_cnt[e]) return;
    const float* row = g_gu + ((size_t)e * T_TOK + r) * TWO_I;
    size_t pbase = ((size_t)e * T_TOK + r) * I_DIM;
    for (int i = threadIdx.x * 2; i < I_DIM; i += 512) {
        float a = silu_f(row[i])     * row[I_DIM + i];
        float b = silu_f(row[i + 1]) * row[I_DIM + i + 1];
        uint32_t h = hi2(a, b), l = lo2(a, b, h);
        ((uint32_t*)c_guhi)[(pbase + i) >> 1] = h;
        ((uint32_t*)c_gulo)[(pbase + i) >> 1] = l;
    }
}

__global__ void __launch_bounds__(256) act_shared() {
    int t = blockIdx.x;
    const float* row = g_sgu + (size_t)t * SH2;
    size_t pbase = (size_t)t * SHI_DIM;
    for (int i = threadIdx.x * 2; i < SHI_DIM; i += 512) {
        float a = silu_f(row[i])     * row[SHI_DIM + i];
        float b = silu_f(row[i + 1]) * row[SHI_DIM + i + 1];
        uint32_t h = hi2(a, b), l = lo2(a, b, h);
        ((uint32_t*)c_sahi)[(pbase + i) >> 1] = h;
        ((uint32_t*)c_salo)[(pbase + i) >> 1] = l;
    }
}

// ---------------- final sum ----------------
__global__ void __launch_bounds__(256) final_sum(float* __restrict__ out) {
    int t = blockIdx.x;
    int e0 = g_texp[t * 4 + 0], e1 = g_texp[t * 4 + 1], e2 = g_texp[t * 4 + 2], e3 = g_texp[t * 4 + 3];
    int r0 = g_trow[t * 4 + 0], r1 = g_trow[t * 4 + 1], r2 = g_trow[t * 4 + 2], r3 = g_trow[t * 4 + 3];
    float w0 = g_twt[t * 4 + 0], w1v = g_twt[t * 4 + 1], w2v = g_twt[t * 4 + 2], w3 = g_twt[t * 4 + 3];
    const float* d0 = g_down + ((size_t)e0 * T_TOK + r0) * H_DIM;
    const float* d1 = g_down + ((size_t)e1 * T_TOK + r1) * H_DIM;
    const float* d2 = g_down + ((size_t)e2 * T_TOK + r2) * H_DIM;
    const float* d3 = g_down + ((size_t)e3 * T_TOK + r3) * H_DIM;
    for (int h = threadIdx.x; h < H_DIM; h += 256) {
        float v = out[(size_t)t * H_DIM + h];
        v += w0 * d0[h] + w1v * d1[h] + w2v * d2[h] + w3 * d3[h];
        out[(size_t)t * H_DIM + h] = v;
    }
}

// ---------------- launch ----------------
extern "C" void kernel_launch(void* const* d_in, const int* in_sizes, int n_in,
                              void* d_out, int out_size) {
    (void)in_sizes; (void)n_in; (void)out_size;
    const float* hidden  = (const float*)d_in[0];
    const float* ln1_w   = (const float*)d_in[2];
    const float* ln2_w   = (const float*)d_in[3];
    const float* q_w     = (const float*)d_in[4];
    const float* kv_w    = (const float*)d_in[5];
    const float* o_w     = (const float*)d_in[6];
    const float* gate_w  = (const float*)d_in[7];
    const float* w1      = (const float*)d_in[8];
    const float* w2      = (const float*)d_in[9];
    const float* sh_gu_w = (const float*)d_in[10];
    const float* sh_dn_w = (const float*)d_in[11];
    float* out = (float*)d_out;

    float *pX, *pQ, *pKV, *pHid, *pX2, *pSgu, *pGu, *pDown;
    cudaGetSymbolAddress((void**)&pX, g_X);
    cudaGetSymbolAddress((void**)&pQ, g_Q);
    cudaGetSymbolAddress((void**)&pKV, g_KV);
    cudaGetSymbolAddress((void**)&pHid, g_hid);
    cudaGetSymbolAddress((void**)&pX2, g_X2);
    cudaGetSymbolAddress((void**)&pSgu, g_sgu);
    cudaGetSymbolAddress((void**)&pGu, g_gu);
    cudaGetSymbolAddress((void**)&pDown, g_down);

    __nv_bfloat16 *Xhi, *Xlo, *athi, *atlo, *X2hi, *X2lo, *guhi, *gulo, *sahi, *salo;
    __nv_bfloat16 *qwhi, *qwlo, *kvhi, *kvlo, *owhi, *owlo, *w1hi, *w1lo, *w2hi, *w2lo, *sghi, *sglo, *sdhi, *sdlo;
    cudaGetSymbolAddress((void**)&Xhi, c_Xhi);   cudaGetSymbolAddress((void**)&Xlo, c_Xlo);
    cudaGetSymbolAddress((void**)&athi, c_athi); cudaGetSymbolAddress((void**)&atlo, c_atlo);
    cudaGetSymbolAddress((void**)&X2hi, c_X2hi); cudaGetSymbolAddress((void**)&X2lo, c_X2lo);
    cudaGetSymbolAddress((void**)&guhi, c_guhi); cudaGetSymbolAddress((void**)&gulo, c_gulo);
    cudaGetSymbolAddress((void**)&sahi, c_sahi); cudaGetSymbolAddress((void**)&salo, c_salo);
    cudaGetSymbolAddress((void**)&qwhi, c_qwhi); cudaGetSymbolAddress((void**)&qwlo, c_qwlo);
    cudaGetSymbolAddress((void**)&kvhi, c_kvhi); cudaGetSymbolAddress((void**)&kvlo, c_kvlo);
    cudaGetSymbolAddress((void**)&owhi, c_owhi); cudaGetSymbolAddress((void**)&owlo, c_owlo);
    cudaGetSymbolAddress((void**)&w1hi, c_w1hi); cudaGetSymbolAddress((void**)&w1lo, c_w1lo);
    cudaGetSymbolAddress((void**)&w2hi, c_w2hi); cudaGetSymbolAddress((void**)&w2lo, c_w2lo);
    cudaGetSymbolAddress((void**)&sghi, c_sghi); cudaGetSymbolAddress((void**)&sglo, c_sglo);
    cudaGetSymbolAddress((void**)&sdhi, c_sdhi); cudaGetSymbolAddress((void**)&sdlo, c_sdlo);

    const int ATTN_SMEM = (64 * 129 + 64 * 129 + 64 * 132 + 64 * 65 + 192) * 4;
    cudaFuncSetAttribute(attn_kernel, cudaFuncAttributeMaxDynamicSharedMemorySize, ATTN_SMEM);
    cudaFuncSetAttribute(gemm_cp<0, false>, cudaFuncAttributeMaxDynamicSharedMemorySize, GSMEM_BYTES);
    cudaFuncSetAttribute(gemm_cp<0, true >, cudaFuncAttributeMaxDynamicSharedMemorySize, GSMEM_BYTES);
    cudaFuncSetAttribute(gemm_cp<1, false>, cudaFuncAttributeMaxDynamicSharedMemorySize, GSMEM_BYTES);
    cudaFuncSetAttribute(gemm_cp<2, false>, cudaFuncAttributeMaxDynamicSharedMemorySize, GSMEM_BYTES);

    // 0) weight conversions (bf16 hi/lo planes)
    conv_qw<<<1024, 256>>>(q_w);
    conv_gen<<<1024, 256>>>(kv_w,    kvhi, kvlo, (long long)4096 * 512);
    conv_gen<<<1024, 256>>>(o_w,     owhi, owlo, (long long)2048 * 512);
    conv_gen<<<2048, 256>>>(w1,      w1hi, w1lo, (long long)E_NUM * TWO_I * 512);
    conv_gen<<<2048, 256>>>(w2,      w2hi, w2lo, (long long)E_NUM * H_DIM * 352);
    conv_gen<<<1024, 256>>>(sh_gu_w, sghi, sglo, (long long)SH2 * 512);
    conv_gen<<<1024, 256>>>(sh_dn_w, sdhi, sdlo, (long long)H_DIM * 704);

    // 1) x = rmsnorm(hidden, ln1_w) -> planes
    rmsnorm_kernel<<<T_TOK, 256>>>(hidden, ln1_w, pX, Xhi, Xlo);
    // 2) Q
    gemm_cp<0, false><<<dim3(16, 16, 1), 256, GSMEM_BYTES>>>(
        Xhi, Xlo, 0LL, H_DIM, qwhi, qwlo, 0LL, pQ, 0LL, 2048, T_TOK, H_DIM, nullptr, 0);
    // 3) KV
    gemm_cp<0, false><<<dim3(32, 16, 1), 256, GSMEM_BYTES>>>(
        Xhi, Xlo, 0LL, H_DIM, kvhi, kvlo, 0LL, pKV, 0LL, 4096, T_TOK, H_DIM, nullptr, 0);
    // 4) attention -> attn planes
    attn_kernel<<<dim3(16, 32), 256, ATTN_SMEM>>>();
    // 5) hid = attn @ o_w^T + hidden
    gemm_cp<0, true><<<dim3(16, 16, 1), 256, GSMEM_BYTES>>>(
        athi, atlo, 0LL, 2048, owhi, owlo, 0LL, pHid, 0LL, H_DIM, T_TOK, 2048, hidden, H_DIM);
    // 6) x2 = rmsnorm(hid, ln2_w) -> fp32 + planes
    rmsnorm_kernel<<<T_TOK, 256>>>(pHid, ln2_w, pX2, X2hi, X2lo);
    // 7) routing
    zero_cnt<<<1, 32>>>();
    gate_kernel<<<T_TOK, 512>>>(gate_w);
    // 8) routed GU
    gemm_cp<1, false><<<dim3(22, 16, E_NUM), 256, GSMEM_BYTES>>>(
        X2hi, X2lo, 0LL, H_DIM, w1hi, w1lo, (long long)TWO_I * H_DIM,
        pGu, (long long)T_TOK * TWO_I, TWO_I, 0, H_DIM, nullptr, 0);
    // 9) routed act -> planes
    act_moe<<<dim3(T_TOK, E_NUM), 256>>>();
    // 10) routed down
    gemm_cp<2, false><<<dim3(16, 16, E_NUM), 256, GSMEM_BYTES>>>(
        guhi, gulo, (long long)T_TOK * I_DIM, I_DIM, w2hi, w2lo, (long long)H_DIM * I_DIM,
        pDown, (long long)T_TOK * H_DIM, H_DIM, 0, I_DIM, nullptr, 0);
    // 11) shared GU
    gemm_cp<0, false><<<dim3(44, 16, 1), 256, GSMEM_BYTES>>>(
        X2hi, X2lo, 0LL, H_DIM, sghi, sglo, 0LL, pSgu, 0LL, SH2, T_TOK, H_DIM, nullptr, 0);
    // 12) shared act -> planes
    act_shared<<<T_TOK, 256>>>();
    // 13) out = act @ sh_dn^T + hid
    gemm_cp<0, true><<<dim3(16, 16, 1), 256, GSMEM_BYTES>>>(
        sahi, salo, 0LL, SHI_DIM, sdhi, sdlo, 0LL, out, 0LL, H_DIM, T_TOK, SHI_DIM, pHid, H_DIM);
    // 14) out += weighted routed contributions
    final_sum<<<T_TOK, 256>>>(out);
}

// round 5
// speedup vs baseline: 2.1566x; 1.0017x over previous
#include <cuda_runtime.h>
#include <cuda_bf16.h>
#include <cstdint>
#include <math.h>

#define T_TOK 2048
#define H_DIM 2048
#define S_LEN 1024
#define NHEAD 16
#define E_NUM 16
#define I_DIM 1408
#define TWO_I 2816
#define SHI_DIM 2816
#define SH2 5632

// ---------------- fp32 scratch ----------------
__device__ float g_X   [(size_t)T_TOK * H_DIM];
__device__ float g_Q   [(size_t)T_TOK * 2048];
__device__ float g_KV  [(size_t)T_TOK * 4096];
__device__ float g_hid [(size_t)T_TOK * H_DIM];
__device__ float g_X2  [(size_t)T_TOK * H_DIM];
__device__ float g_sgu [(size_t)T_TOK * SH2];
__device__ float g_gu  [(size_t)E_NUM * T_TOK * TWO_I];
__device__ float g_down[(size_t)E_NUM * T_TOK * H_DIM];
__device__ int   g_cnt [E_NUM];
__device__ int   g_tok [E_NUM * T_TOK];
__device__ int   g_texp[T_TOK * 4];
__device__ int   g_trow[T_TOK * 4];
__device__ float g_twt [T_TOK * 4];

// ---------------- bf16 hi/lo planes ----------------
__device__ __nv_bfloat16 c_Xhi [(size_t)T_TOK * H_DIM],      c_Xlo [(size_t)T_TOK * H_DIM];
__device__ __nv_bfloat16 c_athi[(size_t)T_TOK * 2048],       c_atlo[(size_t)T_TOK * 2048];
__device__ __nv_bfloat16 c_X2hi[(size_t)T_TOK * H_DIM],      c_X2lo[(size_t)T_TOK * H_DIM];
__device__ __nv_bfloat16 c_guhi[(size_t)E_NUM * T_TOK * I_DIM], c_gulo[(size_t)E_NUM * T_TOK * I_DIM];
__device__ __nv_bfloat16 c_sahi[(size_t)T_TOK * SHI_DIM],    c_salo[(size_t)T_TOK * SHI_DIM];
__device__ __nv_bfloat16 c_qwhi[(size_t)2048 * 2048],        c_qwlo[(size_t)2048 * 2048];
__device__ __nv_bfloat16 c_kvhi[(size_t)4096 * 2048],        c_kvlo[(size_t)4096 * 2048];
__device__ __nv_bfloat16 c_owhi[(size_t)2048 * 2048],        c_owlo[(size_t)2048 * 2048];
__device__ __nv_bfloat16 c_w1hi[(size_t)E_NUM * TWO_I * H_DIM], c_w1lo[(size_t)E_NUM * TWO_I * H_DIM];
__device__ __nv_bfloat16 c_w2hi[(size_t)E_NUM * H_DIM * I_DIM], c_w2lo[(size_t)E_NUM * H_DIM * I_DIM];
__device__ __nv_bfloat16 c_sghi[(size_t)SH2 * H_DIM],        c_sglo[(size_t)SH2 * H_DIM];
__device__ __nv_bfloat16 c_sdhi[(size_t)H_DIM * SHI_DIM],    c_sdlo[(size_t)H_DIM * SHI_DIM];

// ================= helpers =================
static __device__ __forceinline__ uint32_t smem_u32(const void* p) {
    uint32_t a;
    asm("{ .reg .u64 t; cvta.to.shared.u64 t, %1; cvt.u32.u64 %0, t; }" : "=r"(a) : "l"(p));
    return a;
}
static __device__ __forceinline__ uint32_t hi2(float x, float y) {
    uint32_t r;
    asm("prmt.b32 %0, %1, %2, 0x7632;" : "=r"(r) : "r"(__float_as_uint(x)), "r"(__float_as_uint(y)));
    return r;
}
static __device__ __forceinline__ uint32_t lo2(float x, float y, uint32_t h) {
    float hx = __uint_as_float(h << 16);
    float hy = __uint_as_float(h & 0xffff0000u);
    float lx = x - hx, ly = y - hy;
    uint32_t r;
    asm("cvt.rn.bf16x2.f32 %0, %1, %2;" : "=r"(r) : "f"(ly), "f"(lx));
    return r;
}
#define LDM4(r, a) \
    asm volatile("ldmatrix.sync.aligned.m8n8.x4.shared.b16 {%0,%1,%2,%3}, [%4];" \
        : "=r"((r)[0]), "=r"((r)[1]), "=r"((r)[2]), "=r"((r)[3]) : "r"(a))
#define MMA16816(c, a, b0, b1) \
    asm volatile("mma.sync.aligned.m16n8k16.row.col.f32.bf16.bf16.f32 " \
        "{%0,%1,%2,%3}, {%4,%5,%6,%7}, {%8,%9}, {%0,%1,%2,%3};" \
        : "+f"((c)[0]), "+f"((c)[1]), "+f"((c)[2]), "+f"((c)[3]) \
        : "r"((a)[0]), "r"((a)[1]), "r"((a)[2]), "r"((a)[3]), "r"(b0), "r"(b1))
#define CPA16(d, s, n) \
    asm volatile("cp.async.cg.shared.global [%0], [%1], 16, %2;" :: "r"(d), "l"(s), "r"(n) : "memory")
#define CPA_COMMIT() asm volatile("cp.async.commit_group;" ::: "memory")
#define CPA_WAIT2()  asm volatile("cp.async.wait_group 2;" ::: "memory")

// ================= conversion kernels =================
__global__ void __launch_bounds__(256) conv_gen(const float* __restrict__ src,
                                                __nv_bfloat16* __restrict__ dhi,
                                                __nv_bfloat16* __restrict__ dlo,
                                                long long n4) {
    long long stride = (long long)gridDim.x * 256;
    for (long long i = (long long)blockIdx.x * 256 + threadIdx.x; i < n4; i += stride) {
        float4 v = ((const float4*)src)[i];
        uint32_t h0 = hi2(v.x, v.y), h1 = hi2(v.z, v.w);
        uint32_t l0 = lo2(v.x, v.y, h0), l1 = lo2(v.z, v.w, h1);
        ((uint2*)dhi)[i] = make_uint2(h0, h1);
        ((uint2*)dlo)[i] = make_uint2(l0, l1);
    }
}
__global__ void __launch_bounds__(256) conv_qw(const float* __restrict__ src) {
    long long n4 = (long long)2048 * 512;
    long long stride = (long long)gridDim.x * 256;
    for (long long i = (long long)blockIdx.x * 256 + threadIdx.x; i < n4; i += stride) {
        int row = (int)(i >> 9), c4 = (int)(i & 511);
        int sr = (row >> 7) * 192 + (row & 127);
        float4 v = ((const float4*)(src + (long long)sr * 2048))[c4];
        uint32_t h0 = hi2(v.x, v.y), h1 = hi2(v.z, v.w);
        uint32_t l0 = lo2(v.x, v.y, h0), l1 = lo2(v.z, v.w, h1);
        ((uint2*)c_qwhi)[i] = make_uint2(h0, h1);
        ((uint2*)c_qwlo)[i] = make_uint2(l0, l1);
    }
}

// ================= cp.async HMMA bf16x3 GEMM (term-major MMA ordering) =================
#define GSMEM_BYTES (4 * 40960)

template <int MODE, bool ADD>
__global__ void __launch_bounds__(256, 1) gemm_cp(
    const __nv_bfloat16* __restrict__ Ahi, const __nv_bfloat16* __restrict__ Alo,
    long long aestride, int lda,
    const __nv_bfloat16* __restrict__ Bhi, const __nv_bfloat16* __restrict__ Blo,
    long long bestride,
    float* __restrict__ C, long long cstride, int ldc,
    int M, int K,
    const float* __restrict__ addsrc, int ldadd)
{
    extern __shared__ char smem[];
    const int e  = blockIdx.z;
    const int Me = (MODE == 0) ? M : g_cnt[e];
    const int bm = blockIdx.y * 128, bn = blockIdx.x * 128;
    if (bm >= Me) return;
    const __nv_bfloat16* AhiB = Ahi + (MODE == 2 ? (long long)e * aestride : 0LL);
    const __nv_bfloat16* AloB = Alo + (MODE == 2 ? (long long)e * aestride : 0LL);
    const __nv_bfloat16* BhiB = Bhi + (long long)e * bestride;
    const __nv_bfloat16* BloB = Blo + (long long)e * bestride;
    float* Cb = C + (long long)e * cstride;

    const uint32_t sb = smem_u32(smem);
    const int tid = threadIdx.x, wid = tid >> 5, lid = tid & 31;
    const int wm = wid & 3, wn = wid >> 2;

    uint32_t sOff[2]; uint32_t aval[2];
    const char *aHp[2], *aLp[2], *bHp[2], *bLp[2];
    #pragma unroll
    for (int i = 0; i < 2; i++) {
        int q = tid + i * 256;
        int row = q >> 2, seg = q & 3;
        sOff[i] = (uint32_t)(row * 80 + seg * 16);
        int gm = bm + row;
        aval[i] = (gm < Me) ? 16u : 0u;
        long long arow;
        if (MODE == 1) arow = (gm < Me) ? (long long)g_tok[e * T_TOK + gm] : 0LL;
        else           arow = (gm < Me) ? (long long)gm : 0LL;
        aHp[i] = (const char*)(AhiB + arow * (long long)lda) + seg * 16;
        aLp[i] = (const char*)(AloB + arow * (long long)lda) + seg * 16;
        long long brow = (long long)(bn + row);
        bHp[i] = (const char*)(BhiB + brow * (long long)lda) + seg * 16;
        bLp[i] = (const char*)(BloB + brow * (long long)lda) + seg * 16;
    }

    const int laneRow = lid & 15, laneChk = lid >> 4;
    uint32_t aOff[2], bOff[4];
    #pragma unroll
    for (int t = 0; t < 2; t++)
        aOff[t] = (uint32_t)((wm * 32 + t * 16 + laneRow) * 80 + laneChk * 16);
    #pragma unroll
    for (int p = 0; p < 4; p++)
        bOff[p] = (uint32_t)(20480 + (wn * 64 + p * 16 + laneRow) * 80 + laneChk * 16);

    float acc[2][8][4];
    #pragma unroll
    for (int t = 0; t < 2; t++)
        #pragma unroll
        for (int n8 = 0; n8 < 8; n8++)
            #pragma unroll
            for (int j = 0; j < 4; j++) acc[t][n8][j] = 0.f;

    const int NC = K / 32;

    #define ISSUE(c) do { \
        uint32_t st_ = sb + (uint32_t)((c) & 3) * 40960u; \
        long long kb_ = (long long)(c) * 64; \
        _Pragma("unroll") \
        for (int i_ = 0; i_ < 2; i_++) { \
            CPA16(st_ + sOff[i_],          aHp[i_] + kb_, aval[i_]); \
            CPA16(st_ + 10240u + sOff[i_], aLp[i_] + kb_, aval[i_]); \
            CPA16(st_ + 20480u + sOff[i_], bHp[i_] + kb_, 16u); \
            CPA16(st_ + 30720u + sOff[i_], bLp[i_] + kb_, 16u); \
        } \
    } while (0)

    ISSUE(0); CPA_COMMIT();
    if (NC > 1) { ISSUE(1); } CPA_COMMIT();
    if (NC > 2) { ISSUE(2); } CPA_COMMIT();

    for (int c = 0; c < NC; c++) {
        CPA_WAIT2();
        __syncthreads();
        const uint32_t stg = sb + (uint32_t)(c & 3) * 40960u;
        #pragma unroll
        for (int h = 0; h < 2; h++) {
            // load ALL fragments for this k16 step up front
            uint32_t ah0[4], ah1[4], al0[4], al1[4];
            uint32_t bh[4][4], bl[4][4];
            LDM4(ah0, stg + aOff[0] + h * 32);
            LDM4(ah1, stg + aOff[1] + h * 32);
            LDM4(al0, stg + aOff[0] + 10240u + h * 32);
            LDM4(al1, stg + aOff[1] + 10240u + h * 32);
            #pragma unroll
            for (int p = 0; p < 4; p++) LDM4(bh[p], stg + bOff[p] + h * 32);
            #pragma unroll
            for (int p = 0; p < 4; p++) LDM4(bl[p], stg + bOff[p] + 10240u + h * 32);
            // term 1: hi*hi — 16 MMAs, all distinct accumulators
            #pragma unroll
            for (int p = 0; p < 4; p++) {
                MMA16816(acc[0][2 * p],     ah0, bh[p][0], bh[p][2]);
                MMA16816(acc[0][2 * p + 1], ah0, bh[p][1], bh[p][3]);
                MMA16816(acc[1][2 * p],     ah1, bh[p][0], bh[p][2]);
                MMA16816(acc[1][2 * p + 1], ah1, bh[p][1], bh[p][3]);
            }
            // term 2: lo*hi — reuse distance 16
            #pragma unroll
            for (int p = 0; p < 4; p++) {
                MMA16816(acc[0][2 * p],     al0, bh[p][0], bh[p][2]);
                MMA16816(acc[0][2 * p + 1], al0, bh[p][1], bh[p][3]);
                MMA16816(acc[1][2 * p],     al1, bh[p][0], bh[p][2]);
                MMA16816(acc[1][2 * p + 1], al1, bh[p][1], bh[p][3]);
            }
            // term 3: hi*lo — reuse distance 16
            #pragma unroll
            for (int p = 0; p < 4; p++) {
                MMA16816(acc[0][2 * p],     ah0, bl[p][0], bl[p][2]);
                MMA16816(acc[0][2 * p + 1], ah0, bl[p][1], bl[p][3]);
                MMA16816(acc[1][2 * p],     ah1, bl[p][0], bl[p][2]);
                MMA16816(acc[1][2 * p + 1], ah1, bl[p][1], bl[p][3]);
            }
        }
        __syncthreads();
        if (c + 3 < NC) ISSUE(c + 3);
        CPA_COMMIT();
    }
    #undef ISSUE

    const int g = lid >> 2, tg = lid & 3;
    #pragma unroll
    for (int t = 0; t < 2; t++) {
        #pragma unroll
        for (int half = 0; half < 2; half++) {
            int row = bm + wm * 32 + t * 16 + g + half * 8;
            if (row >= Me) continue;
            float* cp = Cb + (long long)row * ldc + bn + wn * 64 + tg * 2;
            const float* ap = ADD ? (addsrc + (long long)row * ldadd + bn + wn * 64 + tg * 2) : (const float*)0;
            #pragma unroll
            for (int n8 = 0; n8 < 8; n8++) {
                float v0 = acc[t][n8][half * 2], v1 = acc[t][n8][half * 2 + 1];
                if (ADD) { v0 += ap[n8 * 8]; v1 += ap[n8 * 8 + 1]; }
                cp[n8 * 8] = v0; cp[n8 * 8 + 1] = v1;
            }
        }
    }
}

// ---------------- rmsnorm (fp32 out + hi/lo planes) ----------------
__global__ __launch_bounds__(256) void rmsnorm_kernel(const float* __restrict__ in,
                                                      const float* __restrict__ w,
                                                      float* __restrict__ out,
                                                      __nv_bfloat16* __restrict__ phi,
                                                      __nv_bfloat16* __restrict__ plo) {
    int t = blockIdx.x;
    const float* row = in + (size_t)t * H_DIM;
    float ss = 0.f;
    for (int i = threadIdx.x; i < H_DIM; i += 256) { float v = row[i]; ss += v * v; }
    __shared__ float red[8];
    #pragma unroll
    for (int o = 16; o; o >>= 1) ss += __shfl_xor_sync(0xffffffffu, ss, o);
    if ((threadIdx.x & 31) == 0) red[threadIdx.x >> 5] = ss;
    __syncthreads();
    if (threadIdx.x < 32) {
        float v = (threadIdx.x < 8) ? red[threadIdx.x] : 0.f;
        #pragma unroll
        for (int o = 4; o; o >>= 1) v += __shfl_xor_sync(0xffffffffu, v, o);
        if (threadIdx.x == 0) red[0] = v;
    }
    __syncthreads();
    float inv = rsqrtf(red[0] * (1.0f / H_DIM) + 1e-6f);
    for (int i = threadIdx.x * 2; i < H_DIM; i += 512) {
        float a = row[i] * inv * w[i];
        float b = row[i + 1] * inv * w[i + 1];
        out[(size_t)t * H_DIM + i] = a;
        out[(size_t)t * H_DIM + i + 1] = b;
        uint32_t h = hi2(a, b), l = lo2(a, b, h);
        ((uint32_t*)phi)[((size_t)t * H_DIM + i) >> 1] = h;
        ((uint32_t*)plo)[((size_t)t * H_DIM + i) >> 1] = l;
    }
}

// ---------------- flash attention (fp32, causal, D=128; writes bf16 planes) ----------------
__global__ void __launch_bounds__(256) attn_kernel() {
    extern __shared__ float sm[];
    float* Qs = sm;
    float* Ks = Qs + 64 * 129;
    float* Vs = Ks + 64 * 129;
    float* Ps = Vs + 64 * 132;
    float* mrow = Ps + 64 * 65;
    float* lrow = mrow + 64;
    float* corr = lrow + 64;

    int bh = blockIdx.y; int b = bh >> 4, h = bh & 15;
    int q0 = blockIdx.x * 64;
    int tb = b * S_LEN;
    int tid = threadIdx.x;
    int ty = tid / 16, tx = tid % 16;

    for (int i = tid; i < 64 * 32; i += 256) {
        int r = i >> 5, c4 = (i & 31) * 4;
        float4 v = *(const float4*)(g_Q + (size_t)(tb + q0 + r) * 2048 + h * 128 + c4);
        Qs[r * 129 + c4] = v.x; Qs[r * 129 + c4 + 1] = v.y;
        Qs[r * 129 + c4 + 2] = v.z; Qs[r * 129 + c4 + 3] = v.w;
    }
    if (tid < 64) { mrow[tid] = -1e30f; lrow[tid] = 0.f; }
    float acc[4][8];
    #pragma unroll
    for (int i = 0; i < 4; i++)
        #pragma unroll
        for (int j = 0; j < 8; j++) acc[i][j] = 0.f;
    const float scale = 1.0f / sqrtf(192.0f);
    __syncthreads();

    int nkt = blockIdx.x + 1;
    for (int kt = 0; kt < nkt; kt++) {
        int k0 = kt * 64;
        for (int i = tid; i < 64 * 32; i += 256) {
            int r = i >> 5, c4 = (i & 31) * 4;
            const float* kp = g_KV + (size_t)(tb + k0 + r) * 4096 + h * 128;
            float4 kv4 = *(const float4*)(kp + c4);
            Ks[r * 129 + c4] = kv4.x; Ks[r * 129 + c4 + 1] = kv4.y;
            Ks[r * 129 + c4 + 2] = kv4.z; Ks[r * 129 + c4 + 3] = kv4.w;
            float4 vv4 = *(const float4*)(kp + 2048 + c4);
            Vs[r * 132 + c4] = vv4.x; Vs[r * 132 + c4 + 1] = vv4.y;
            Vs[r * 132 + c4 + 2] = vv4.z; Vs[r * 132 + c4 + 3] = vv4.w;
        }
        __syncthreads();
        float s[4][4];
        #pragma unroll
        for (int i = 0; i < 4; i++)
            #pragma unroll
            for (int j = 0; j < 4; j++) s[i][j] = 0.f;
        #pragma unroll 4
        for (int k = 0; k < 128; k++) {
            float qa[4], kb[4];
            #pragma unroll
            for (int i = 0; i < 4; i++) qa[i] = Qs[(4 * ty + i) * 129 + k];
            #pragma unroll
            for (int j = 0; j < 4; j++) kb[j] = Ks[(4 * tx + j) * 129 + k];
            #pragma unroll
            for (int i = 0; i < 4; i++)
                #pragma unroll
                for (int j = 0; j < 4; j++) s[i][j] += qa[i] * kb[j];
        }
        #pragma unroll
        for (int i = 0; i < 4; i++)
            #pragma unroll
            for (int j = 0; j < 4; j++) {
                int rq = q0 + 4 * ty + i, ck = k0 + 4 * tx + j;
                Ps[(4 * ty + i) * 65 + 4 * tx + j] = (ck <= rq) ? s[i][j] * scale : -1e30f;
            }
        __syncthreads();
        if (tid < 64) {
            float m0 = mrow[tid], mx = m0;
            for (int c = 0; c < 64; c++) mx = fmaxf(mx, Ps[tid * 65 + c]);
            float cr = __expf(m0 - mx);
            float l = lrow[tid] * cr;
            for (int c = 0; c < 64; c++) {
                float p = __expf(Ps[tid * 65 + c] - mx);
                Ps[tid * 65 + c] = p; l += p;
            }
            mrow[tid] = mx; lrow[tid] = l; corr[tid] = cr;
        }
        __syncthreads();
        #pragma unroll
        for (int i = 0; i < 4; i++) {
            float cr = corr[4 * ty + i];
            #pragma unroll
            for (int j = 0; j < 8; j++) acc[i][j] *= cr;
        }
        #pragma unroll 2
        for (int c = 0; c < 64; c++) {
            float p[4], v[8];
            #pragma unroll
            for (int i = 0; i < 4; i++) p[i] = Ps[(4 * ty + i) * 65 + c];
            #pragma unroll
            for (int j = 0; j < 8; j++) v[j] = Vs[c * 132 + 8 * tx + j];
            #pragma unroll
            for (int i = 0; i < 4; i++)
                #pragma unroll
                for (int j = 0; j < 8; j++) acc[i][j] += p[i] * v[j];
        }
        __syncthreads();
    }
    #pragma unroll
    for (int i = 0; i < 4; i++) {
        int r = 4 * ty + i;
        float inv = 1.0f / lrow[r];
        float v[8];
        #pragma unroll
        for (int j = 0; j < 8; j++) v[j] = acc[i][j] * inv;
        size_t base = (size_t)(tb + q0 + r) * 2048 + h * 128 + 8 * tx;
        uint32_t h0 = hi2(v[0], v[1]), h1 = hi2(v[2], v[3]), h2 = hi2(v[4], v[5]), h3 = hi2(v[6], v[7]);
        uint32_t l0 = lo2(v[0], v[1], h0), l1 = lo2(v[2], v[3], h1);
        uint32_t l2 = lo2(v[4], v[5], h2), l3 = lo2(v[6], v[7], h3);
        *(uint2*)(c_athi + base)     = make_uint2(h0, h1);
        *(uint2*)(c_athi + base + 4) = make_uint2(h2, h3);
        *(uint2*)(c_atlo + base)     = make_uint2(l0, l1);
        *(uint2*)(c_atlo + base + 4) = make_uint2(l2, l3);
    }
}

// ---------------- gate ----------------
__global__ void __launch_bounds__(512) zero_cnt() { if (threadIdx.x < E_NUM) g_cnt[threadIdx.x] = 0; }

__global__ void __launch_bounds__(512) gate_kernel(const float* __restrict__ gate_w) {
    int t = blockIdx.x;
    int w = threadIdx.x >> 5, lane = threadIdx.x & 31;
    const float* x = g_X2 + (size_t)t * H_DIM;
    const float* gw = gate_w + (size_t)w * H_DIM;
    float s = 0.f;
    for (int i = lane; i < H_DIM; i += 32) s += x[i] * gw[i];
    #pragma unroll
    for (int o = 16; o; o >>= 1) s += __shfl_xor_sync(0xffffffffu, s, o);
    __shared__ float lg[E_NUM];
    if (lane == 0) lg[w] = s;
    __syncthreads();
    if (threadIdx.x == 0) {
        float mx = -1e30f;
        for (int e = 0; e < E_NUM; e++) mx = fmaxf(mx, lg[e]);
        float pe[E_NUM];
        for (int e = 0; e < E_NUM; e++) pe[e] = expf(lg[e] - mx);
        bool used[E_NUM];
        for (int e = 0; e < E_NUM; e++) used[e] = false;
        int sel[4]; float sw[4]; float wsum = 0.f;
        for (int j = 0; j < 4; j++) {
            int bi = -1; float bv = -1.f;
            for (int e = 0; e < E_NUM; e++)
                if (!used[e] && pe[e] > bv) { bv = pe[e]; bi = e; }
            used[bi] = true; sel[j] = bi; sw[j] = bv; wsum += bv;
        }
        for (int j = 0; j < 4; j++) {
            int e = sel[j];
            int pos = atomicAdd(&g_cnt[e], 1);
            g_tok[e * T_TOK + pos] = t;
            g_texp[t * 4 + j] = e;
            g_trow[t * 4 + j] = pos;
            g_twt [t * 4 + j] = sw[j] / wsum;
        }
    }
}

// ---------------- activations (write bf16 planes) ----------------
__device__ __forceinline__ float silu_f(float x) { return x / (1.0f + __expf(-x)); }

__global__ void __launch_bounds__(256) act_moe() {
    int e = blockIdx.y;
    int r = blockIdx.x;
    if (r >= g_cnt[e]) return;
    const float* row = g_gu + ((size_t)e * T_TOK + r) * TWO_I;
    size_t pbase = ((size_t)e * T_TOK + r) * I_DIM;
    for (int i = threadIdx.x * 2; i < I_DIM; i += 512) {
        float a = silu_f(row[i])     * row[I_DIM + i];
        float b = silu_f(row[i + 1]) * row[I_DIM + i + 1];
        uint32_t h = hi2(a, b), l = lo2(a, b, h);
        ((uint32_t*)c_guhi)[(pbase + i) >> 1] = h;
        ((uint32_t*)c_gulo)[(pbase + i) >> 1] = l;
    }
}

__global__ void __launch_bounds__(256) act_shared() {
    int t = blockIdx.x;
    const float* row = g_sgu + (size_t)t * SH2;
    size_t pbase = (size_t)t * SHI_DIM;
    for (int i = threadIdx.x * 2; i < SHI_DIM; i += 512) {
        float a = silu_f(row[i])     * row[SHI_DIM + i];
        float b = silu_f(row[i + 1]) * row[SHI_DIM + i + 1];
        uint32_t h = hi2(a, b), l = lo2(a, b, h);
        ((uint32_t*)c_sahi)[(pbase + i) >> 1] = h;
        ((uint32_t*)c_salo)[(pbase + i) >> 1] = l;
    }
}

// ---------------- final sum ----------------
__global__ void __launch_bounds__(256) final_sum(float* __restrict__ out) {
    int t = blockIdx.x;
    int e0 = g_texp[t * 4 + 0], e1 = g_texp[t * 4 + 1], e2 = g_texp[t * 4 + 2], e3 = g_texp[t * 4 + 3];
    int r0 = g_trow[t * 4 + 0], r1 = g_trow[t * 4 + 1], r2 = g_trow[t * 4 + 2], r3 = g_trow[t * 4 + 3];
    float w0 = g_twt[t * 4 + 0], w1v = g_twt[t * 4 + 1], w2v = g_twt[t * 4 + 2], w3 = g_twt[t * 4 + 3];
    const float* d0 = g_down + ((size_t)e0 * T_TOK + r0) * H_DIM;
    const float* d1 = g_down + ((size_t)e1 * T_TOK + r1) * H_DIM;
    const float* d2 = g_down + ((size_t)e2 * T_TOK + r2) * H_DIM;
    const float* d3 = g_down + ((size_t)e3 * T_TOK + r3) * H_DIM;
    for (int h = threadIdx.x; h < H_DIM; h += 256) {
        float v = out[(size_t)t * H_DIM + h];
        v += w0 * d0[h] + w1v * d1[h] + w2v * d2[h] + w3 * d3[h];
        out[(size_t)t * H_DIM + h] = v;
    }
}

// ---------------- launch ----------------
extern "C" void kernel_launch(void* const* d_in, const int* in_sizes, int n_in,
                              void* d_out, int out_size) {
    (void)in_sizes; (void)n_in; (void)out_size;
    const float* hidden  = (const float*)d_in[0];
    const float* ln1_w   = (const float*)d_in[2];
    const float* ln2_w   = (const float*)d_in[3];
    const float* q_w     = (const float*)d_in[4];
    const float* kv_w    = (const float*)d_in[5];
    const float* o_w     = (const float*)d_in[6];
    const float* gate_w  = (const float*)d_in[7];
    const float* w1      = (const float*)d_in[8];
    const float* w2      = (const float*)d_in[9];
    const float* sh_gu_w = (const float*)d_in[10];
    const float* sh_dn_w = (const float*)d_in[11];
    float* out = (float*)d_out;

    float *pX, *pQ, *pKV, *pHid, *pX2, *pSgu, *pGu, *pDown;
    cudaGetSymbolAddress((void**)&pX, g_X);
    cudaGetSymbolAddress((void**)&pQ, g_Q);
    cudaGetSymbolAddress((void**)&pKV, g_KV);
    cudaGetSymbolAddress((void**)&pHid, g_hid);
    cudaGetSymbolAddress((void**)&pX2, g_X2);
    cudaGetSymbolAddress((void**)&pSgu, g_sgu);
    cudaGetSymbolAddress((void**)&pGu, g_gu);
    cudaGetSymbolAddress((void**)&pDown, g_down);

    __nv_bfloat16 *Xhi, *Xlo, *athi, *atlo, *X2hi, *X2lo, *guhi, *gulo, *sahi, *salo;
    __nv_bfloat16 *qwhi, *qwlo, *kvhi, *kvlo, *owhi, *owlo, *w1hi, *w1lo, *w2hi, *w2lo, *sghi, *sglo, *sdhi, *sdlo;
    cudaGetSymbolAddress((void**)&Xhi, c_Xhi);   cudaGetSymbolAddress((void**)&Xlo, c_Xlo);
    cudaGetSymbolAddress((void**)&athi, c_athi); cudaGetSymbolAddress((void**)&atlo, c_atlo);
    cudaGetSymbolAddress((void**)&X2hi, c_X2hi); cudaGetSymbolAddress((void**)&X2lo, c_X2lo);
    cudaGetSymbolAddress((void**)&guhi, c_guhi); cudaGetSymbolAddress((void**)&gulo, c_gulo);
    cudaGetSymbolAddress((void**)&sahi, c_sahi); cudaGetSymbolAddress((void**)&salo, c_salo);
    cudaGetSymbolAddress((void**)&qwhi, c_qwhi); cudaGetSymbolAddress((void**)&qwlo, c_qwlo);
    cudaGetSymbolAddress((void**)&kvhi, c_kvhi); cudaGetSymbolAddress((void**)&kvlo, c_kvlo);
    cudaGetSymbolAddress((void**)&owhi, c_owhi); cudaGetSymbolAddress((void**)&owlo, c_owlo);
    cudaGetSymbolAddress((void**)&w1hi, c_w1hi); cudaGetSymbolAddress((void**)&w1lo, c_w1lo);
    cudaGetSymbolAddress((void**)&w2hi, c_w2hi); cudaGetSymbolAddress((void**)&w2lo, c_w2lo);
    cudaGetSymbolAddress((void**)&sghi, c_sghi); cudaGetSymbolAddress((void**)&sglo, c_sglo);
    cudaGetSymbolAddress((void**)&sdhi, c_sdhi); cudaGetSymbolAddress((void**)&sdlo, c_sdlo);

    const int ATTN_SMEM = (64 * 129 + 64 * 129 + 64 * 132 + 64 * 65 + 192) * 4;
    cudaFuncSetAttribute(attn_kernel, cudaFuncAttributeMaxDynamicSharedMemorySize, ATTN_SMEM);
    cudaFuncSetAttribute(gemm_cp<0, false>, cudaFuncAttributeMaxDynamicSharedMemorySize, GSMEM_BYTES);
    cudaFuncSetAttribute(gemm_cp<0, true >, cudaFuncAttributeMaxDynamicSharedMemorySize, GSMEM_BYTES);
    cudaFuncSetAttribute(gemm_cp<1, false>, cudaFuncAttributeMaxDynamicSharedMemorySize, GSMEM_BYTES);
    cudaFuncSetAttribute(gemm_cp<2, false>, cudaFuncAttributeMaxDynamicSharedMemorySize, GSMEM_BYTES);

    conv_qw<<<1024, 256>>>(q_w);
    conv_gen<<<1024, 256>>>(kv_w,    kvhi, kvlo, (long long)4096 * 512);
    conv_gen<<<1024, 256>>>(o_w,     owhi, owlo, (long long)2048 * 512);
    conv_gen<<<2048, 256>>>(w1,      w1hi, w1lo, (long long)E_NUM * TWO_I * 512);
    conv_gen<<<2048, 256>>>(w2,      w2hi, w2lo, (long long)E_NUM * H_DIM * 352);
    conv_gen<<<1024, 256>>>(sh_gu_w, sghi, sglo, (long long)SH2 * 512);
    conv_gen<<<1024, 256>>>(sh_dn_w, sdhi, sdlo, (long long)H_DIM * 704);

    rmsnorm_kernel<<<T_TOK, 256>>>(hidden, ln1_w, pX, Xhi, Xlo);
    gemm_cp<0, false><<<dim3(16, 16, 1), 256, GSMEM_BYTES>>>(
        Xhi, Xlo, 0LL, H_DIM, qwhi, qwlo, 0LL, pQ, 0LL, 2048, T_TOK, H_DIM, nullptr, 0);
    gemm_cp<0, false><<<dim3(32, 16, 1), 256, GSMEM_BYTES>>>(
        Xhi, Xlo, 0LL, H_DIM, kvhi, kvlo, 0LL, pKV, 0LL, 4096, T_TOK, H_DIM, nullptr, 0);
    attn_kernel<<<dim3(16, 32), 256, ATTN_SMEM>>>();
    gemm_cp<0, true><<<dim3(16, 16, 1), 256, GSMEM_BYTES>>>(
        athi, atlo, 0LL, 2048, owhi, owlo, 0LL, pHid, 0LL, H_DIM, T_TOK, 2048, hidden, H_DIM);
    rmsnorm_kernel<<<T_TOK, 256>>>(pHid, ln2_w, pX2, X2hi, X2lo);
    zero_cnt<<<1, 32>>>();
    gate_kernel<<<T_TOK, 512>>>(gate_w);
    gemm_cp<1, false><<<dim3(22, 16, E_NUM), 256, GSMEM_BYTES>>>(
        X2hi, X2lo, 0LL, H_DIM, w1hi, w1lo, (long long)TWO_I * H_DIM,
        pGu, (long long)T_TOK * TWO_I, TWO_I, 0, H_DIM, nullptr, 0);
    act_moe<<<dim3(T_TOK, E_NUM), 256>>>();
    gemm_cp<2, false><<<dim3(16, 16, E_NUM), 256, GSMEM_BYTES>>>(
        guhi, gulo, (long long)T_TOK * I_DIM, I_DIM, w2hi, w2lo, (long long)H_DIM * I_DIM,
        pDown, (long long)T_TOK * H_DIM, H_DIM, 0, I_DIM, nullptr, 0);
    gemm_cp<0, false><<<dim3(44, 16, 1), 256, GSMEM_BYTES>>>(
        X2hi, X2lo, 0LL, H_DIM, sghi, sglo, 0LL, pSgu, 0LL, SH2, T_TOK, H_DIM, nullptr, 0);
    act_shared<<<T_TOK, 256>>>();
    gemm_cp<0, true><<<dim3(16, 16, 1), 256, GSMEM_BYTES>>>(
        sahi, salo, 0LL, SHI_DIM, sdhi, sdlo, 0LL, out, 0LL, H_DIM, T_TOK, SHI_DIM, pHid, H_DIM);
    final_sum<<<T_TOK, 256>>>(out);
}